// round 10
// baseline (speedup 1.0000x reference)
#include <cuda_runtime.h>
#include <cuda_fp16.h>
#include <cstddef>
#include <cstdint>

// Problem constants (fixed by the dataset)
#define TT 128
#define BB 64
#define EE 1024
#define HH 1024
#define VV 10000
#define LL 2

#define MREST (127 * 64)   // 8128 rows for t = 1..127

// ---------------- scratch (device globals; no allocations allowed) ----------
__device__ __align__(256) __half g_bufA[MREST * 1024];
__device__ __align__(256) __half g_bufB[MREST * 1024];
__device__ float g_x0 [BB * EE];
__device__ float g_xt [BB * EE];
__device__ float g_xt2[BB * EE];
__device__ float g_h0 [2 * BB * HH];           // h00 | h01
__device__ float g_aU [2 * BB * HH];           // aU0 | aU1
__device__ float g_part[8 * 64 * 10016];       // split-K partials (max use)
__device__ int   g_cnt[1024];                  // zero-init; self-resetting
__device__ __align__(256) __half g_WwH[LL * HH * EE];   // fp16 weights
__device__ __align__(256) __half g_FwH[LL * EE * HH];
__device__ __align__(256) __half g_DwH[VV * HH];

// ---------------- fp32 -> fp16 weight conversion ----------------------------
__global__ void f2h_kernel(const float* __restrict__ src,
                           __half* __restrict__ dst, int n4)
{
    int i = blockIdx.x * blockDim.x + threadIdx.x;
    if (i >= n4) return;
    float4 v = reinterpret_cast<const float4*>(src)[i];
    __half2 lo = __floats2half2_rn(v.x, v.y);
    __half2 hi = __floats2half2_rn(v.z, v.w);
    uint2 o;
    o.x = *reinterpret_cast<unsigned*>(&lo);
    o.y = *reinterpret_cast<unsigned*>(&hi);
    reinterpret_cast<uint2*>(dst)[i] = o;
}

// ---------------- embedding gathers ------------------------------------------
__global__ void gather_emb_f(const int* __restrict__ inputs,
                             const float* __restrict__ emb,
                             float* __restrict__ X,
                             int ioff, int nrows)
{
    int idx = blockIdx.x * blockDim.x + threadIdx.x;
    int total = nrows * 256;
    if (idx >= total) return;
    int r = idx >> 8;
    int c = idx & 255;
    int tok = inputs[r + ioff];
    reinterpret_cast<float4*>(X)[(size_t)r * 256 + c] =
        reinterpret_cast<const float4*>(emb)[(size_t)tok * 256 + c];
}

__global__ void gather_emb_h(const int* __restrict__ inputs,
                             const float* __restrict__ emb,
                             __half* __restrict__ X,
                             int ioff, int nrows)
{
    int idx = blockIdx.x * blockDim.x + threadIdx.x;
    int total = nrows * 256;
    if (idx >= total) return;
    int r = idx >> 8;
    int c = idx & 255;
    int tok = inputs[r + ioff];
    float4 v = reinterpret_cast<const float4*>(emb)[(size_t)tok * 256 + c];
    __half2 lo = __floats2half2_rn(v.x, v.y);
    __half2 hi = __floats2half2_rn(v.z, v.w);
    uint2 o;
    o.x = *reinterpret_cast<unsigned*>(&lo);
    o.y = *reinterpret_cast<unsigned*>(&hi);
    reinterpret_cast<uint2*>(X)[(size_t)r * 256 + c] = o;
}

// =======================================================================
// Phase A: fused split-K GEMM (M=64) — one kernel per stage.
// Each CTA computes a 64x64xkc partial; the LAST CTA per (z, n-block)
// (atomic counter) reduces across splits in fixed order + runs epilogue,
// then resets its counter (deterministic, graph-replay safe).
// grid = (ceil(N/64), nsplit, batch), block = 256.
// =======================================================================
template <int EPI>
__global__ __launch_bounds__(256)
void sgemm_fused(int N, int K,
                 const float* __restrict__ A,
                 const float* __restrict__ W,
                 const float* __restrict__ bias,
                 const float* __restrict__ aU,
                 float* __restrict__ C,
                 float* __restrict__ O,
                 int l, int row_off,
                 size_t aStr, size_t wStr, size_t bStr, size_t cStr,
                 float* __restrict__ part, int* __restrict__ cnt)
{
    const int z = blockIdx.z;
    const int nsplit = gridDim.y;
    const float* Ab = A + z * aStr;
    const float* Wb = W + z * wStr;
    const float* Bb = bias + z * bStr;
    float* Cb = C ? C + z * cStr : nullptr;
    float* Pb = part + (size_t)z * nsplit * 64 * N;

    __shared__ float As[8][68];
    __shared__ float Ws[8][68];
    __shared__ int s_last;

    const int tid = threadIdx.x;
    const int bn  = blockIdx.x * 64;
    const int s   = blockIdx.y;
    const int kc  = K / nsplit;
    const int k0  = s * kc;

    const int tx = tid & 15;
    const int ty = tid >> 4;
    const int lr = tid >> 2;
    const int lk = (tid & 3) * 2;

    float acc[4][4];
#pragma unroll
    for (int i = 0; i < 4; i++)
#pragma unroll
        for (int j = 0; j < 4; j++) acc[i][j] = 0.0f;

    const int gn = bn + lr;
    const bool okW = gn < N;

    for (int kk = 0; kk < kc; kk += 8) {
        float2 av = *reinterpret_cast<const float2*>(&Ab[(size_t)lr * K + k0 + kk + lk]);
        float2 wv = make_float2(0.f, 0.f);
        if (okW)
            wv = *reinterpret_cast<const float2*>(&Wb[(size_t)gn * K + k0 + kk + lk]);
        As[lk][lr] = av.x;  As[lk + 1][lr] = av.y;
        Ws[lk][lr] = wv.x;  Ws[lk + 1][lr] = wv.y;
        __syncthreads();

#pragma unroll
        for (int k = 0; k < 8; k++) {
            float a[4], b[4];
#pragma unroll
            for (int i = 0; i < 4; i++) a[i] = As[k][ty * 4 + i];
#pragma unroll
            for (int j = 0; j < 4; j++) b[j] = Ws[k][tx * 4 + j];
#pragma unroll
            for (int i = 0; i < 4; i++)
#pragma unroll
                for (int j = 0; j < 4; j++)
                    acc[i][j] = fmaf(a[i], b[j], acc[i][j]);
        }
        __syncthreads();
    }

    // write partial
#pragma unroll
    for (int i = 0; i < 4; i++) {
        int m = ty * 4 + i;
#pragma unroll
        for (int j = 0; j < 4; j++) {
            int n = bn + tx * 4 + j;
            if (n < N)
                Pb[((size_t)s * 64 + m) * N + n] = acc[i][j];
        }
    }

    // last-CTA reduction protocol (threadFenceReduction pattern)
    __threadfence();
    __syncthreads();
    if (tid == 0) {
        int r = atomicAdd(&cnt[z * gridDim.x + blockIdx.x], 1);
        s_last = (r == nsplit - 1);
    }
    __syncthreads();
    if (!s_last) return;
    __threadfence();

    // reduce across splits (fixed order) + epilogue for this 64x64 block
    for (int e = tid; e < 64 * 64; e += 256) {
        int m = e >> 6;
        int n = bn + (e & 63);
        if (n >= N) continue;
        float acc2 = 0.0f;
        for (int ss = 0; ss < nsplit; ss++)
            acc2 += Pb[((size_t)ss * 64 + m) * N + n];
        float v = acc2 + Bb[n];
        if (EPI == 0) {
            Cb[(size_t)m * N + n] = v;
        } else if (EPI == 1) {
            Cb[(size_t)m * N + n] = tanhf(v);
        } else if (EPI == 2) {
            v += aU[(size_t)m * N + n];
            v = tanhf(v);
            Cb[(size_t)m * N + n] = v;
            O[(((size_t)0 * LL + l) * BB + m) * HH + n] = v;
        } else { // EPI == 3
            O[(size_t)(m + row_off) * N + n] = v;
        }
    }

    __syncthreads();
    if (tid == 0)
        atomicExch(&cnt[z * gridDim.x + blockIdx.x], 0);   // reset for replay
}

// =======================================================================
// Big GEMM on tensor cores: fp16 mma.sync.m16n8k16 + ldmatrix,
// 3-stage cp.async pipeline, 128x256 block tile, 8 warps of 64x64.
// =======================================================================
#define CBM 128
#define CBN 256
#define CBK 32                        // halves per K-chunk (64 B data/row)
#define NSTG 3
#define HSTR 40                       // row stride in halves (80 B, conflict-free)
#define ABUF_BYTES (CBM * HSTR * 2)   // 10240
#define WBUF_BYTES (CBN * HSTR * 2)   // 20480
#define SMEM_BYTES (NSTG * (ABUF_BYTES + WBUF_BYTES))   // 92160

__device__ __forceinline__ void cp_async16(uint32_t saddr, const void* gptr, bool ok) {
    int sz = ok ? 16 : 0;
    asm volatile("cp.async.cg.shared.global [%0], [%1], 16, %2;\n"
                 :: "r"(saddr), "l"(gptr), "r"(sz));
}

__device__ __forceinline__ void mma_f16(float c[4], const unsigned a[4],
                                        unsigned b0, unsigned b1) {
    asm volatile("mma.sync.aligned.m16n8k16.row.col.f32.f16.f16.f32 "
                 "{%0,%1,%2,%3}, {%4,%5,%6,%7}, {%8,%9}, {%0,%1,%2,%3};"
                 : "+f"(c[0]), "+f"(c[1]), "+f"(c[2]), "+f"(c[3])
                 : "r"(a[0]), "r"(a[1]), "r"(a[2]), "r"(a[3]),
                   "r"(b0), "r"(b1));
}

__device__ __forceinline__ void ldsm_x4(unsigned r[4], uint32_t saddr) {
    asm volatile("ldmatrix.sync.aligned.m8n8.x4.shared.b16 {%0,%1,%2,%3}, [%4];"
                 : "=r"(r[0]), "=r"(r[1]), "=r"(r[2]), "=r"(r[3]) : "r"(saddr));
}

template <int EPI>
__global__ __launch_bounds__(256, 1)
void hgemm(int M, int N, int K,
           const __half* __restrict__ A,
           const __half* __restrict__ W,
           const float* __restrict__ bias,
           const float* __restrict__ aU,
           __half* __restrict__ C,
           float* __restrict__ O,
           int t0, int l, int row_off)
{
    extern __shared__ char smraw[];

    const int tid  = threadIdx.x;
    const int lane = tid & 31;
    const int wid  = tid >> 5;
    const int wm   = (wid & 1) * 64;     // warp M offset
    const int wn   = (wid >> 1) * 64;    // warp N offset
    const int grp  = lane >> 2;
    const int tig  = lane & 3;

    const int bm = blockIdx.x * CBM;     // M fastest-varying
    const int bn = blockIdx.y * CBN;

    uint32_t sbase;
    asm("{ .reg .u64 t; cvta.to.shared.u64 t, %1; cvt.u32.u64 %0, t; }"
        : "=r"(sbase) : "l"(smraw));

    bool aok[2];  const __half* agp[2];  uint32_t asm_[2];
#pragma unroll
    for (int i = 0; i < 2; i++) {
        int slot = tid + 256 * i;
        int row = slot >> 2, seg = slot & 3;
        aok[i] = (bm + row) < M;
        agp[i] = A + (size_t)(aok[i] ? bm + row : 0) * K + seg * 8;
        asm_[i] = sbase + (uint32_t)(row * (HSTR * 2) + seg * 16);
    }
    bool wok[4];  const __half* wgp[4];  uint32_t wsm_[4];
#pragma unroll
    for (int i = 0; i < 4; i++) {
        int slot = tid + 256 * i;
        int row = slot >> 2, seg = slot & 3;
        wok[i] = (bn + row) < N;
        wgp[i] = W + (size_t)(wok[i] ? bn + row : 0) * K + seg * 8;
        wsm_[i] = sbase + (uint32_t)(NSTG * ABUF_BYTES + row * (HSTR * 2) + seg * 16);
    }

    const int lrow = lane & 15;
    const int lcol = lane >> 4;
    uint32_t aoff[4], boff[4];
#pragma unroll
    for (int mf = 0; mf < 4; mf++)
        aoff[mf] = (uint32_t)((wm + mf * 16 + lrow) * (HSTR * 2) + lcol * 16);
#pragma unroll
    for (int p = 0; p < 4; p++)
        boff[p] = (uint32_t)((wn + p * 16 + lrow) * (HSTR * 2) + lcol * 16);

    float acc[4][8][4];
#pragma unroll
    for (int mf = 0; mf < 4; mf++)
#pragma unroll
        for (int nf = 0; nf < 8; nf++)
#pragma unroll
            for (int r = 0; r < 4; r++) acc[mf][nf][r] = 0.0f;

    const int kT = K / CBK;

#pragma unroll
    for (int s = 0; s < NSTG - 1; s++) {
#pragma unroll
        for (int i = 0; i < 2; i++)
            cp_async16(asm_[i] + s * ABUF_BYTES, agp[i] + s * CBK, aok[i]);
#pragma unroll
        for (int i = 0; i < 4; i++)
            cp_async16(wsm_[i] + s * WBUF_BYTES, wgp[i] + s * CBK, wok[i]);
        asm volatile("cp.async.commit_group;\n");
    }

    for (int kt = 0; kt < kT; kt++) {
        asm volatile("cp.async.wait_group %0;\n" :: "n"(NSTG - 2));
        __syncthreads();

        const int pf = kt + NSTG - 1;
        if (pf < kT) {
            const int ps = pf % NSTG;
#pragma unroll
            for (int i = 0; i < 2; i++)
                cp_async16(asm_[i] + ps * ABUF_BYTES, agp[i] + pf * CBK, aok[i]);
#pragma unroll
            for (int i = 0; i < 4; i++)
                cp_async16(wsm_[i] + ps * WBUF_BYTES, wgp[i] + pf * CBK, wok[i]);
        }
        asm volatile("cp.async.commit_group;\n");

        const int cb = kt % NSTG;
        const uint32_t abase = sbase + cb * ABUF_BYTES;
        const uint32_t wbase = sbase + NSTG * ABUF_BYTES + cb * WBUF_BYTES;

#pragma unroll
        for (int ks = 0; ks < 2; ks++) {          // two k16 steps per chunk
            const uint32_t kb = ks * 32;          // 16 halves = 32 bytes
            unsigned af[4][4], bf[4][4];
#pragma unroll
            for (int mf = 0; mf < 4; mf++)
                ldsm_x4(af[mf], abase + aoff[mf] + kb);
#pragma unroll
            for (int p = 0; p < 4; p++)
                ldsm_x4(bf[p], wbase + boff[p] + kb);
#pragma unroll
            for (int mf = 0; mf < 4; mf++)
#pragma unroll
                for (int p = 0; p < 4; p++) {
                    mma_f16(acc[mf][2 * p],     af[mf], bf[p][0], bf[p][2]);
                    mma_f16(acc[mf][2 * p + 1], af[mf], bf[p][1], bf[p][3]);
                }
        }
    }

    // ---- epilogue ----
#pragma unroll
    for (int mf = 0; mf < 4; mf++) {
#pragma unroll
        for (int rh = 0; rh < 2; rh++) {
            int gm = bm + wm + mf * 16 + grp + rh * 8;
            if (gm >= M) continue;
#pragma unroll
            for (int nf = 0; nf < 8; nf++) {
                int gn = bn + wn + nf * 8 + tig * 2;
                if (gn >= N) continue;            // N even → gn+1 ok
                float v0 = acc[mf][nf][rh * 2 + 0] + bias[gn];
                float v1 = acc[mf][nf][rh * 2 + 1] + bias[gn + 1];
                if (EPI == 1) {
                    v0 = tanhf(v0); v1 = tanhf(v1);
                    __half2 h = __floats2half2_rn(v0, v1);
                    *reinterpret_cast<__half2*>(&C[(size_t)gm * N + gn]) = h;
                } else if (EPI == 2) {
                    const float2 au = *reinterpret_cast<const float2*>(
                        &aU[(size_t)(gm & 63) * N + gn]);
                    v0 = tanhf(v0 + au.x);
                    v1 = tanhf(v1 + au.y);
                    __half2 h = __floats2half2_rn(v0, v1);
                    *reinterpret_cast<__half2*>(&C[(size_t)gm * N + gn]) = h;
                    int t = t0 + (gm >> 6);
                    int b = gm & 63;
                    *reinterpret_cast<float2*>(
                        &O[(((size_t)t * LL + l) * BB + b) * HH + gn]) =
                        make_float2(v0, v1);      // h_all output: exact tanh
                } else { // EPI == 3 (logits, exact fp32)
                    *reinterpret_cast<float2*>(&O[(size_t)(gm + row_off) * N + gn]) =
                        make_float2(v0, v1);
                }
            }
        }
    }
}

// ---------------- host-side orchestration -----------------------------------
static inline dim3 hgrid(int M, int N) {
    return dim3((M + CBM - 1) / CBM, (N + CBN - 1) / CBN);
}

extern "C" void kernel_launch(void* const* d_in, const int* in_sizes, int n_in,
                              void* d_out, int out_size)
{
    (void)in_sizes; (void)n_in; (void)out_size;
    const int*   inputs = (const int*)  d_in[0];
    const float* hidden = (const float*)d_in[1];   // (L,B,H)
    const float* emb    = (const float*)d_in[2];   // (V,E)
    const float* Ww     = (const float*)d_in[3];   // (L,H,E)
    const float* Wb     = (const float*)d_in[4];   // (L,H)
    const float* Uw     = (const float*)d_in[5];   // (L,H,H)
    const float* Ub     = (const float*)d_in[6];   // (L,H)
    const float* Fw     = (const float*)d_in[7];   // (L,E,H)
    const float* Fb     = (const float*)d_in[8];   // (L,E)
    const float* Dw     = (const float*)d_in[9];   // (V,H)
    const float* Db     = (const float*)d_in[10];  // (V,)

    float* out  = (float*)d_out;
    float* hall = out + (size_t)TT * BB * VV;      // h_all after logits

    __half *bufA, *bufB, *WwH, *FwH, *DwH;
    float *x0, *xt, *xt2, *h0, *aU, *part;
    int* cnt;
    cudaGetSymbolAddress((void**)&bufA, g_bufA);
    cudaGetSymbolAddress((void**)&bufB, g_bufB);
    cudaGetSymbolAddress((void**)&x0,  g_x0);
    cudaGetSymbolAddress((void**)&xt,  g_xt);
    cudaGetSymbolAddress((void**)&xt2, g_xt2);
    cudaGetSymbolAddress((void**)&h0,  g_h0);
    cudaGetSymbolAddress((void**)&aU,  g_aU);
    cudaGetSymbolAddress((void**)&part, g_part);
    cudaGetSymbolAddress((void**)&cnt, g_cnt);
    cudaGetSymbolAddress((void**)&WwH, g_WwH);
    cudaGetSymbolAddress((void**)&FwH, g_FwH);
    cudaGetSymbolAddress((void**)&DwH, g_DwH);

    float* h00 = h0;
    float* h01 = h0 + (size_t)BB * HH;
    float* aU0 = aU;
    float* aU1 = aU + (size_t)BB * HH;

    cudaFuncSetAttribute(hgemm<1>, cudaFuncAttributeMaxDynamicSharedMemorySize, SMEM_BYTES);
    cudaFuncSetAttribute(hgemm<2>, cudaFuncAttributeMaxDynamicSharedMemorySize, SMEM_BYTES);
    cudaFuncSetAttribute(hgemm<3>, cudaFuncAttributeMaxDynamicSharedMemorySize, SMEM_BYTES);

    const size_t Wstride = (size_t)HH * EE;
    const size_t BH = (size_t)BB * HH;

    // ---- convert weights to fp16 ----
    {
        int n4;
        n4 = (LL * HH * EE) / 4;
        f2h_kernel<<<(n4 + 255) / 256, 256>>>(Ww, WwH, n4);
        n4 = (LL * EE * HH) / 4;
        f2h_kernel<<<(n4 + 255) / 256, 256>>>(Fw, FwH, n4);
        n4 = (VV * HH) / 4;
        f2h_kernel<<<(n4 + 255) / 256, 256>>>(Dw, DwH, n4);
    }

    // ---- Phase A: t = 0 — fused split-K stages (one kernel each) ----
    gather_emb_f<<<(BB * 256 + 255) / 256, 256>>>(inputs, emb, x0, 0, BB);

    // aU-init pair: aU[z] = hidden[z] @ Uw[z]^T + Ub[z]
    sgemm_fused<0><<<dim3(16, 32, 2), 256>>>(HH, HH, hidden, Uw, Ub, nullptr,
                                             aU, nullptr, 0, 0,
                                             BH, Wstride, HH, BH, part, cnt);
    // h00 = tanh(x0 @ Ww0^T + Wb0 + aU0)
    sgemm_fused<2><<<dim3(16, 32, 1), 256>>>(HH, EE, x0, Ww, Wb, aU0,
                                             h00, hall, 0, 0,
                                             0, 0, 0, 0, part, cnt);
    // xt = tanh(h00 @ Fw0^T + Fb0)
    sgemm_fused<1><<<dim3(16, 32, 1), 256>>>(EE, HH, h00, Fw, Fb, nullptr,
                                             xt, nullptr, 0, 0,
                                             0, 0, 0, 0, part, cnt);
    // h01 = tanh(xt @ Ww1^T + Wb1 + aU1)
    sgemm_fused<2><<<dim3(16, 32, 1), 256>>>(HH, EE, xt, Ww + Wstride, Wb + HH, aU1,
                                             h01, hall, 1, 0,
                                             0, 0, 0, 0, part, cnt);
    // xt2 = tanh(h01 @ Fw1^T + Fb1)
    sgemm_fused<1><<<dim3(16, 32, 1), 256>>>(EE, HH, h01, Fw + Wstride, Fb + EE, nullptr,
                                             xt2, nullptr, 0, 0,
                                             0, 0, 0, 0, part, cnt);
    // logits[0] = xt2 @ Dw^T + Db  (rows 0..63 of out)
    sgemm_fused<3><<<dim3((VV + 63) / 64, 8, 1), 256>>>(VV, HH, xt2, Dw, Db, nullptr,
                                                        nullptr, out, 0, 0,
                                                        0, 0, 0, 0, part, cnt);
    // aU-final pair: aU[z] = h0[z] @ Uw[z]^T + Ub[z]
    sgemm_fused<0><<<dim3(16, 32, 2), 256>>>(HH, HH, h0, Uw, Ub, nullptr,
                                             aU, nullptr, 0, 0,
                                             BH, Wstride, HH, BH, part, cnt);

    // ---- Phase B: t = 1..127 batched (M = 8128) on fp16 tensor cores ----
    gather_emb_h<<<(MREST * 256 + 255) / 256, 256>>>(inputs, emb, bufA, BB, MREST);

    hgemm<2><<<hgrid(MREST, HH), 256, SMEM_BYTES>>>(MREST, HH, EE, bufA, WwH, Wb,
                                                    aU0, bufB, hall, 1, 0, 0);
    hgemm<1><<<hgrid(MREST, EE), 256, SMEM_BYTES>>>(MREST, EE, HH, bufB, FwH, Fb,
                                                    nullptr, bufA, nullptr, 0, 0, 0);
    hgemm<2><<<hgrid(MREST, HH), 256, SMEM_BYTES>>>(MREST, HH, EE, bufA,
                                                    WwH + Wstride, Wb + HH,
                                                    aU1, bufB, hall, 1, 1, 0);
    hgemm<1><<<hgrid(MREST, EE), 256, SMEM_BYTES>>>(MREST, EE, HH, bufB,
                                                    FwH + Wstride, Fb + EE,
                                                    nullptr, bufA, nullptr, 0, 0, 0);
    hgemm<3><<<hgrid(MREST, VV), 256, SMEM_BYTES>>>(MREST, VV, HH, bufA, DwH, Db,
                                                    nullptr, nullptr, out, 0, 0, BB);
}

// round 11
// speedup vs baseline: 1.1479x; 1.1479x over previous
#include <cuda_runtime.h>
#include <cuda_fp16.h>
#include <cstddef>
#include <cstdint>

// Problem constants (fixed by the dataset)
#define TT 128
#define BB 64
#define EE 1024
#define HH 1024
#define VV 10000
#define LL 2

#define MREST (127 * 64)   // 8128 rows for t = 1..127

// ---------------- scratch (device globals; no allocations allowed) ----------
__device__ __align__(256) __half g_bufA[MREST * 1024];
__device__ __align__(256) __half g_bufB[MREST * 1024];
__device__ float g_x0 [BB * EE];
__device__ float g_xt [BB * EE];
__device__ float g_xt2[BB * EE];
__device__ float g_h0 [2 * BB * HH];           // h00 | h01
__device__ float g_aU [2 * BB * HH];           // aU0 | aU1
__device__ float g_part[8 * 64 * 10016];       // split-K partials
__device__ __align__(256) __half g_WwH[LL * HH * EE];   // fp16 weights
__device__ __align__(256) __half g_FwH[LL * EE * HH];
__device__ __align__(256) __half g_DwH[VV * HH];

// ---------------- fp32 -> fp16 weight conversion ----------------------------
__global__ void f2h_kernel(const float* __restrict__ src,
                           __half* __restrict__ dst, int n4)
{
    int i = blockIdx.x * blockDim.x + threadIdx.x;
    if (i >= n4) return;
    float4 v = reinterpret_cast<const float4*>(src)[i];
    __half2 lo = __floats2half2_rn(v.x, v.y);
    __half2 hi = __floats2half2_rn(v.z, v.w);
    uint2 o;
    o.x = *reinterpret_cast<unsigned*>(&lo);
    o.y = *reinterpret_cast<unsigned*>(&hi);
    reinterpret_cast<uint2*>(dst)[i] = o;
}

// ---------------- embedding gathers ------------------------------------------
__global__ void gather_emb_f(const int* __restrict__ inputs,
                             const float* __restrict__ emb,
                             float* __restrict__ X,
                             int ioff, int nrows)
{
    int idx = blockIdx.x * blockDim.x + threadIdx.x;
    int total = nrows * 256;
    if (idx >= total) return;
    int r = idx >> 8;
    int c = idx & 255;
    int tok = inputs[r + ioff];
    reinterpret_cast<float4*>(X)[(size_t)r * 256 + c] =
        reinterpret_cast<const float4*>(emb)[(size_t)tok * 256 + c];
}

__global__ void gather_emb_h(const int* __restrict__ inputs,
                             const float* __restrict__ emb,
                             __half* __restrict__ X,
                             int ioff, int nrows)
{
    int idx = blockIdx.x * blockDim.x + threadIdx.x;
    int total = nrows * 256;
    if (idx >= total) return;
    int r = idx >> 8;
    int c = idx & 255;
    int tok = inputs[r + ioff];
    float4 v = reinterpret_cast<const float4*>(emb)[(size_t)tok * 256 + c];
    __half2 lo = __floats2half2_rn(v.x, v.y);
    __half2 hi = __floats2half2_rn(v.z, v.w);
    uint2 o;
    o.x = *reinterpret_cast<unsigned*>(&lo);
    o.y = *reinterpret_cast<unsigned*>(&hi);
    reinterpret_cast<uint2*>(X)[(size_t)r * 256 + c] = o;
}

// =======================================================================
// Small-M (M=64) split-K fp32 GEMM (Phase A), batchable via grid.z
// =======================================================================
__global__ __launch_bounds__(256)
void sgemm_splitk(int N, int K,
                  const float* __restrict__ A,
                  const float* __restrict__ W,
                  float* __restrict__ partial,
                  size_t aStride, size_t wStride, size_t pStride)
{
    const float* Ab = A + blockIdx.z * aStride;
    const float* Wb = W + blockIdx.z * wStride;
    float* Pb = partial + blockIdx.z * pStride;

    __shared__ float As[8][68];
    __shared__ float Ws[8][68];

    const int tid = threadIdx.x;
    const int bn  = blockIdx.x * 64;
    const int s   = blockIdx.y;
    const int kc  = K / gridDim.y;
    const int k0  = s * kc;

    const int tx = tid & 15;
    const int ty = tid >> 4;
    const int lr = tid >> 2;
    const int lk = (tid & 3) * 2;

    float acc[4][4];
#pragma unroll
    for (int i = 0; i < 4; i++)
#pragma unroll
        for (int j = 0; j < 4; j++) acc[i][j] = 0.0f;

    const int gn = bn + lr;
    const bool okW = gn < N;

    for (int kk = 0; kk < kc; kk += 8) {
        float2 av = *reinterpret_cast<const float2*>(&Ab[(size_t)lr * K + k0 + kk + lk]);
        float2 wv = make_float2(0.f, 0.f);
        if (okW)
            wv = *reinterpret_cast<const float2*>(&Wb[(size_t)gn * K + k0 + kk + lk]);
        As[lk][lr] = av.x;  As[lk + 1][lr] = av.y;
        Ws[lk][lr] = wv.x;  Ws[lk + 1][lr] = wv.y;
        __syncthreads();

#pragma unroll
        for (int k = 0; k < 8; k++) {
            float a[4], b[4];
#pragma unroll
            for (int i = 0; i < 4; i++) a[i] = As[k][ty * 4 + i];
#pragma unroll
            for (int j = 0; j < 4; j++) b[j] = Ws[k][tx * 4 + j];
#pragma unroll
            for (int i = 0; i < 4; i++)
#pragma unroll
                for (int j = 0; j < 4; j++)
                    acc[i][j] = fmaf(a[i], b[j], acc[i][j]);
        }
        __syncthreads();
    }

#pragma unroll
    for (int i = 0; i < 4; i++) {
        int m = ty * 4 + i;
#pragma unroll
        for (int j = 0; j < 4; j++) {
            int n = bn + tx * 4 + j;
            if (n < N)
                Pb[((size_t)s * 64 + m) * N + n] = acc[i][j];
        }
    }
}

template <int EPI>
__global__ void splitk_epi(int N, int nsplit,
                           const float* __restrict__ partial,
                           const float* __restrict__ bias,
                           const float* __restrict__ aU,
                           float* __restrict__ C,
                           float* __restrict__ O,
                           int l, int row_off,
                           size_t pStride, size_t bStride, size_t cStride)
{
    const float* Pb = partial + blockIdx.y * pStride;
    const float* Bb = bias + blockIdx.y * bStride;
    float* Cb = C ? C + blockIdx.y * cStride : nullptr;

    int idx = blockIdx.x * blockDim.x + threadIdx.x;
    if (idx >= 64 * N) return;
    int m = idx / N;
    int n = idx - m * N;
    float acc = 0.0f;
    for (int s = 0; s < nsplit; s++)
        acc += Pb[((size_t)s * 64 + m) * N + n];
    float v = acc + Bb[n];
    if (EPI == 0) {
        Cb[(size_t)m * N + n] = v;
    } else if (EPI == 1) {
        Cb[(size_t)m * N + n] = tanhf(v);
    } else if (EPI == 2) {
        v += aU[(size_t)m * N + n];
        v = tanhf(v);
        Cb[(size_t)m * N + n] = v;
        O[(((size_t)0 * LL + l) * BB + m) * HH + n] = v;
    } else { // EPI == 3
        O[(size_t)(m + row_off) * N + n] = v;
    }
}

// =======================================================================
// Big GEMM on tensor cores: fp16 mma.sync.m16n8k16 + ldmatrix,
// 3-stage cp.async pipeline, 128x256 block tile, 8 warps of 64x64.
// A, W are __half (pre-rounded); accumulate fp32; epilogues fused.
// =======================================================================
#define CBM 128
#define CBN 256
#define CBK 32                        // halves per K-chunk (64 B data/row)
#define NSTG 3
#define HSTR 40                       // row stride in halves (80 B, conflict-free)
#define ABUF_BYTES (CBM * HSTR * 2)   // 10240
#define WBUF_BYTES (CBN * HSTR * 2)   // 20480
#define SMEM_BYTES (NSTG * (ABUF_BYTES + WBUF_BYTES))   // 92160

__device__ __forceinline__ void cp_async16(uint32_t saddr, const void* gptr, bool ok) {
    int sz = ok ? 16 : 0;
    asm volatile("cp.async.cg.shared.global [%0], [%1], 16, %2;\n"
                 :: "r"(saddr), "l"(gptr), "r"(sz));
}

__device__ __forceinline__ void mma_f16(float c[4], const unsigned a[4],
                                        unsigned b0, unsigned b1) {
    asm volatile("mma.sync.aligned.m16n8k16.row.col.f32.f16.f16.f32 "
                 "{%0,%1,%2,%3}, {%4,%5,%6,%7}, {%8,%9}, {%0,%1,%2,%3};"
                 : "+f"(c[0]), "+f"(c[1]), "+f"(c[2]), "+f"(c[3])
                 : "r"(a[0]), "r"(a[1]), "r"(a[2]), "r"(a[3]),
                   "r"(b0), "r"(b1));
}

__device__ __forceinline__ void ldsm_x4(unsigned r[4], uint32_t saddr) {
    asm volatile("ldmatrix.sync.aligned.m8n8.x4.shared.b16 {%0,%1,%2,%3}, [%4];"
                 : "=r"(r[0]), "=r"(r[1]), "=r"(r[2]), "=r"(r[3]) : "r"(saddr));
}

template <int EPI>
__global__ __launch_bounds__(256, 1)
void hgemm(int M, int N, int K,
           const __half* __restrict__ A,
           const __half* __restrict__ W,
           const float* __restrict__ bias,
           const float* __restrict__ aU,
           __half* __restrict__ C,
           float* __restrict__ O,
           int t0, int l, int row_off)
{
    extern __shared__ char smraw[];

    const int tid  = threadIdx.x;
    const int lane = tid & 31;
    const int wid  = tid >> 5;
    const int wm   = (wid & 1) * 64;     // warp M offset
    const int wn   = (wid >> 1) * 64;    // warp N offset
    const int grp  = lane >> 2;
    const int tig  = lane & 3;

    const int bm = blockIdx.x * CBM;     // M fastest-varying
    const int bn = blockIdx.y * CBN;

    uint32_t sbase;
    asm("{ .reg .u64 t; cvta.to.shared.u64 t, %1; cvt.u32.u64 %0, t; }"
        : "=r"(sbase) : "l"(smraw));

    bool aok[2];  const __half* agp[2];  uint32_t asm_[2];
#pragma unroll
    for (int i = 0; i < 2; i++) {
        int slot = tid + 256 * i;
        int row = slot >> 2, seg = slot & 3;
        aok[i] = (bm + row) < M;
        agp[i] = A + (size_t)(aok[i] ? bm + row : 0) * K + seg * 8;
        asm_[i] = sbase + (uint32_t)(row * (HSTR * 2) + seg * 16);
    }
    bool wok[4];  const __half* wgp[4];  uint32_t wsm_[4];
#pragma unroll
    for (int i = 0; i < 4; i++) {
        int slot = tid + 256 * i;
        int row = slot >> 2, seg = slot & 3;
        wok[i] = (bn + row) < N;
        wgp[i] = W + (size_t)(wok[i] ? bn + row : 0) * K + seg * 8;
        wsm_[i] = sbase + (uint32_t)(NSTG * ABUF_BYTES + row * (HSTR * 2) + seg * 16);
    }

    const int lrow = lane & 15;
    const int lcol = lane >> 4;
    uint32_t aoff[4], boff[4];
#pragma unroll
    for (int mf = 0; mf < 4; mf++)
        aoff[mf] = (uint32_t)((wm + mf * 16 + lrow) * (HSTR * 2) + lcol * 16);
#pragma unroll
    for (int p = 0; p < 4; p++)
        boff[p] = (uint32_t)((wn + p * 16 + lrow) * (HSTR * 2) + lcol * 16);

    float acc[4][8][4];
#pragma unroll
    for (int mf = 0; mf < 4; mf++)
#pragma unroll
        for (int nf = 0; nf < 8; nf++)
#pragma unroll
            for (int r = 0; r < 4; r++) acc[mf][nf][r] = 0.0f;

    const int kT = K / CBK;

#pragma unroll
    for (int s = 0; s < NSTG - 1; s++) {
#pragma unroll
        for (int i = 0; i < 2; i++)
            cp_async16(asm_[i] + s * ABUF_BYTES, agp[i] + s * CBK, aok[i]);
#pragma unroll
        for (int i = 0; i < 4; i++)
            cp_async16(wsm_[i] + s * WBUF_BYTES, wgp[i] + s * CBK, wok[i]);
        asm volatile("cp.async.commit_group;\n");
    }

    for (int kt = 0; kt < kT; kt++) {
        asm volatile("cp.async.wait_group %0;\n" :: "n"(NSTG - 2));
        __syncthreads();

        const int pf = kt + NSTG - 1;
        if (pf < kT) {
            const int ps = pf % NSTG;
#pragma unroll
            for (int i = 0; i < 2; i++)
                cp_async16(asm_[i] + ps * ABUF_BYTES, agp[i] + pf * CBK, aok[i]);
#pragma unroll
            for (int i = 0; i < 4; i++)
                cp_async16(wsm_[i] + ps * WBUF_BYTES, wgp[i] + pf * CBK, wok[i]);
        }
        asm volatile("cp.async.commit_group;\n");

        const int cb = kt % NSTG;
        const uint32_t abase = sbase + cb * ABUF_BYTES;
        const uint32_t wbase = sbase + NSTG * ABUF_BYTES + cb * WBUF_BYTES;

#pragma unroll
        for (int ks = 0; ks < 2; ks++) {          // two k16 steps per chunk
            const uint32_t kb = ks * 32;          // 16 halves = 32 bytes
            unsigned af[4][4], bf[4][4];
#pragma unroll
            for (int mf = 0; mf < 4; mf++)
                ldsm_x4(af[mf], abase + aoff[mf] + kb);
#pragma unroll
            for (int p = 0; p < 4; p++)
                ldsm_x4(bf[p], wbase + boff[p] + kb);
#pragma unroll
            for (int mf = 0; mf < 4; mf++)
#pragma unroll
                for (int p = 0; p < 4; p++) {
                    mma_f16(acc[mf][2 * p],     af[mf], bf[p][0], bf[p][2]);
                    mma_f16(acc[mf][2 * p + 1], af[mf], bf[p][1], bf[p][3]);
                }
        }
    }

    // ---- epilogue ----
#pragma unroll
    for (int mf = 0; mf < 4; mf++) {
#pragma unroll
        for (int rh = 0; rh < 2; rh++) {
            int gm = bm + wm + mf * 16 + grp + rh * 8;
            if (gm >= M) continue;
#pragma unroll
            for (int nf = 0; nf < 8; nf++) {
                int gn = bn + wn + nf * 8 + tig * 2;
                if (gn >= N) continue;            // N even → gn+1 ok
                float v0 = acc[mf][nf][rh * 2 + 0] + bias[gn];
                float v1 = acc[mf][nf][rh * 2 + 1] + bias[gn + 1];
                if (EPI == 1) {
                    v0 = tanhf(v0); v1 = tanhf(v1);
                    __half2 h = __floats2half2_rn(v0, v1);
                    *reinterpret_cast<__half2*>(&C[(size_t)gm * N + gn]) = h;
                } else if (EPI == 2) {
                    const float2 au = *reinterpret_cast<const float2*>(
                        &aU[(size_t)(gm & 63) * N + gn]);
                    v0 = tanhf(v0 + au.x);
                    v1 = tanhf(v1 + au.y);
                    __half2 h = __floats2half2_rn(v0, v1);
                    *reinterpret_cast<__half2*>(&C[(size_t)gm * N + gn]) = h;
                    int t = t0 + (gm >> 6);
                    int b = gm & 63;
                    *reinterpret_cast<float2*>(
                        &O[(((size_t)t * LL + l) * BB + b) * HH + gn]) =
                        make_float2(v0, v1);      // h_all output: exact tanh
                } else { // EPI == 3 (logits, exact fp32)
                    *reinterpret_cast<float2*>(&O[(size_t)(gm + row_off) * N + gn]) =
                        make_float2(v0, v1);
                }
            }
        }
    }
}

// ---------------- host-side orchestration -----------------------------------
static inline dim3 hgrid(int M, int N) {
    return dim3((M + CBM - 1) / CBM, (N + CBN - 1) / CBN);
}

template <int EPI>
static void small_gemm(int N, int K, int nsplit,
                       const float* A, const float* W, const float* bias,
                       const float* aU, float* C, float* O,
                       int l, int row_off, float* part)
{
    dim3 g((N + 63) / 64, nsplit, 1);
    sgemm_splitk<<<g, 256>>>(N, K, A, W, part, 0, 0, 0);
    int total = 64 * N;
    splitk_epi<EPI><<<dim3((total + 255) / 256, 1), 256>>>(
        N, nsplit, part, bias, aU, C, O, l, row_off, 0, 0, 0);
}

static void small_gemm_pair(int N, int K, int nsplit,
                            const float* A, size_t aStr,
                            const float* W, size_t wStr,
                            const float* bias, size_t bStr,
                            float* C, size_t cStr, float* part)
{
    size_t pStr = (size_t)nsplit * 64 * N;
    dim3 g((N + 63) / 64, nsplit, 2);
    sgemm_splitk<<<g, 256>>>(N, K, A, W, part, aStr, wStr, pStr);
    int total = 64 * N;
    splitk_epi<0><<<dim3((total + 255) / 256, 2), 256>>>(
        N, nsplit, part, bias, nullptr, C, nullptr, 0, 0, pStr, bStr, cStr);
}

extern "C" void kernel_launch(void* const* d_in, const int* in_sizes, int n_in,
                              void* d_out, int out_size)
{
    (void)in_sizes; (void)n_in; (void)out_size;
    const int*   inputs = (const int*)  d_in[0];
    const float* hidden = (const float*)d_in[1];   // (L,B,H)
    const float* emb    = (const float*)d_in[2];   // (V,E)
    const float* Ww     = (const float*)d_in[3];   // (L,H,E)
    const float* Wb     = (const float*)d_in[4];   // (L,H)
    const float* Uw     = (const float*)d_in[5];   // (L,H,H)
    const float* Ub     = (const float*)d_in[6];   // (L,H)
    const float* Fw     = (const float*)d_in[7];   // (L,E,H)
    const float* Fb     = (const float*)d_in[8];   // (L,E)
    const float* Dw     = (const float*)d_in[9];   // (V,H)
    const float* Db     = (const float*)d_in[10];  // (V,)

    float* out  = (float*)d_out;
    float* hall = out + (size_t)TT * BB * VV;      // h_all after logits

    __half *bufA, *bufB, *WwH, *FwH, *DwH;
    float *x0, *xt, *xt2, *h0, *aU, *part;
    cudaGetSymbolAddress((void**)&bufA, g_bufA);
    cudaGetSymbolAddress((void**)&bufB, g_bufB);
    cudaGetSymbolAddress((void**)&x0,  g_x0);
    cudaGetSymbolAddress((void**)&xt,  g_xt);
    cudaGetSymbolAddress((void**)&xt2, g_xt2);
    cudaGetSymbolAddress((void**)&h0,  g_h0);
    cudaGetSymbolAddress((void**)&aU,  g_aU);
    cudaGetSymbolAddress((void**)&part, g_part);
    cudaGetSymbolAddress((void**)&WwH, g_WwH);
    cudaGetSymbolAddress((void**)&FwH, g_FwH);
    cudaGetSymbolAddress((void**)&DwH, g_DwH);

    float* h00 = h0;
    float* h01 = h0 + (size_t)BB * HH;
    float* aU0 = aU;
    float* aU1 = aU + (size_t)BB * HH;

    cudaFuncSetAttribute(hgemm<1>, cudaFuncAttributeMaxDynamicSharedMemorySize, SMEM_BYTES);
    cudaFuncSetAttribute(hgemm<2>, cudaFuncAttributeMaxDynamicSharedMemorySize, SMEM_BYTES);
    cudaFuncSetAttribute(hgemm<3>, cudaFuncAttributeMaxDynamicSharedMemorySize, SMEM_BYTES);

    const size_t Wstride = (size_t)HH * EE;
    const size_t BH = (size_t)BB * HH;

    // ---- convert weights to fp16 ----
    {
        int n4;
        n4 = (LL * HH * EE) / 4;
        f2h_kernel<<<(n4 + 255) / 256, 256>>>(Ww, WwH, n4);
        n4 = (LL * EE * HH) / 4;
        f2h_kernel<<<(n4 + 255) / 256, 256>>>(Fw, FwH, n4);
        n4 = (VV * HH) / 4;
        f2h_kernel<<<(n4 + 255) / 256, 256>>>(Dw, DwH, n4);
    }

    // ---- Phase A: t = 0 (sequential small GEMMs, M = 64, split-K fp32) ----
    gather_emb_f<<<(BB * 256 + 255) / 256, 256>>>(inputs, emb, x0, 0, BB);

    small_gemm_pair(HH, HH, 32, hidden, BH, Uw, Wstride,
                    Ub, HH, aU, BH, part);
    small_gemm<2>(HH, EE, 32, x0, Ww, Wb, aU0, h00, hall, 0, 0, part);
    small_gemm<1>(EE, HH, 32, h00, Fw, Fb, nullptr, xt, nullptr, 0, 0, part);
    small_gemm<2>(HH, EE, 32, xt, Ww + Wstride, Wb + HH, aU1, h01, hall, 1, 0, part);
    small_gemm<1>(EE, HH, 32, h01, Fw + Wstride, Fb + EE, nullptr, xt2, nullptr, 0, 0, part);
    small_gemm<3>(VV, HH, 8, xt2, Dw, Db, nullptr, nullptr, out, 0, 0, part);

    // ---- fixed recurrent terms for t >= 1 (pair, from h00/h01) ----
    small_gemm_pair(HH, HH, 32, h0, BH, Uw, Wstride,
                    Ub, HH, aU, BH, part);

    // ---- Phase B: t = 1..127 batched (M = 8128) on fp16 tensor cores ----
    gather_emb_h<<<(MREST * 256 + 255) / 256, 256>>>(inputs, emb, bufA, BB, MREST);

    hgemm<2><<<hgrid(MREST, HH), 256, SMEM_BYTES>>>(MREST, HH, EE, bufA, WwH, Wb,
                                                    aU0, bufB, hall, 1, 0, 0);
    hgemm<1><<<hgrid(MREST, EE), 256, SMEM_BYTES>>>(MREST, EE, HH, bufB, FwH, Fb,
                                                    nullptr, bufA, nullptr, 0, 0, 0);
    hgemm<2><<<hgrid(MREST, HH), 256, SMEM_BYTES>>>(MREST, HH, EE, bufA,
                                                    WwH + Wstride, Wb + HH,
                                                    aU1, bufB, hall, 1, 1, 0);
    hgemm<1><<<hgrid(MREST, EE), 256, SMEM_BYTES>>>(MREST, EE, HH, bufB,
                                                    FwH + Wstride, Fb + EE,
                                                    nullptr, bufA, nullptr, 0, 0, 0);
    hgemm<3><<<hgrid(MREST, VV), 256, SMEM_BYTES>>>(MREST, VV, HH, bufA, DwH, Db,
                                                    nullptr, nullptr, out, 0, 0, BB);
}

// round 12
// speedup vs baseline: 1.2102x; 1.0543x over previous
#include <cuda_runtime.h>
#include <cuda_fp16.h>
#include <cstddef>
#include <cstdint>

// Problem constants (fixed by the dataset)
#define TT 128
#define BB 64
#define EE 1024
#define HH 1024
#define VV 10000
#define LL 2

#define MREST (127 * 64)   // 8128 rows for t = 1..127

// ---------------- scratch (device globals; no allocations allowed) ----------
__device__ __align__(256) __half g_bufA[MREST * 1024];
__device__ __align__(256) __half g_bufB[MREST * 1024];
__device__ float g_x0 [BB * EE];
__device__ float g_xt [BB * EE];
__device__ float g_xt2[BB * EE];
__device__ float g_h0 [2 * BB * HH];           // h00 | h01
__device__ float g_aU [2 * BB * HH];           // aU0 | aU1
__device__ float g_part[8 * 64 * 10016];       // split-K partials
__device__ __align__(256) __half g_WwH[LL * HH * EE];   // fp16 weights
__device__ __align__(256) __half g_FwH[LL * EE * HH];
__device__ __align__(256) __half g_DwH[VV * HH];

// ---------------- fp32 -> fp16 weight conversion ----------------------------
__global__ void f2h_kernel(const float* __restrict__ src,
                           __half* __restrict__ dst, int n4)
{
    int i = blockIdx.x * blockDim.x + threadIdx.x;
    if (i >= n4) return;
    float4 v = reinterpret_cast<const float4*>(src)[i];
    __half2 lo = __floats2half2_rn(v.x, v.y);
    __half2 hi = __floats2half2_rn(v.z, v.w);
    uint2 o;
    o.x = *reinterpret_cast<unsigned*>(&lo);
    o.y = *reinterpret_cast<unsigned*>(&hi);
    reinterpret_cast<uint2*>(dst)[i] = o;
}

// ---------------- embedding gathers ------------------------------------------
__global__ void gather_emb_f(const int* __restrict__ inputs,
                             const float* __restrict__ emb,
                             float* __restrict__ X,
                             int ioff, int nrows)
{
    int idx = blockIdx.x * blockDim.x + threadIdx.x;
    int total = nrows * 256;
    if (idx >= total) return;
    int r = idx >> 8;
    int c = idx & 255;
    int tok = inputs[r + ioff];
    reinterpret_cast<float4*>(X)[(size_t)r * 256 + c] =
        reinterpret_cast<const float4*>(emb)[(size_t)tok * 256 + c];
}

__global__ void gather_emb_h(const int* __restrict__ inputs,
                             const float* __restrict__ emb,
                             __half* __restrict__ X,
                             int ioff, int nrows)
{
    int idx = blockIdx.x * blockDim.x + threadIdx.x;
    int total = nrows * 256;
    if (idx >= total) return;
    int r = idx >> 8;
    int c = idx & 255;
    int tok = inputs[r + ioff];
    float4 v = reinterpret_cast<const float4*>(emb)[(size_t)tok * 256 + c];
    __half2 lo = __floats2half2_rn(v.x, v.y);
    __half2 hi = __floats2half2_rn(v.z, v.w);
    uint2 o;
    o.x = *reinterpret_cast<unsigned*>(&lo);
    o.y = *reinterpret_cast<unsigned*>(&hi);
    reinterpret_cast<uint2*>(X)[(size_t)r * 256 + c] = o;
}

// =======================================================================
// Small-M (M=64) split-K fp32 GEMM (Phase A), batchable via grid.z
// =======================================================================
__global__ __launch_bounds__(256)
void sgemm_splitk(int N, int K,
                  const float* __restrict__ A,
                  const float* __restrict__ W,
                  float* __restrict__ partial,
                  size_t aStride, size_t wStride, size_t pStride)
{
    const float* Ab = A + blockIdx.z * aStride;
    const float* Wb = W + blockIdx.z * wStride;
    float* Pb = partial + blockIdx.z * pStride;

    __shared__ float As[8][68];
    __shared__ float Ws[8][68];

    const int tid = threadIdx.x;
    const int bn  = blockIdx.x * 64;
    const int s   = blockIdx.y;
    const int kc  = K / gridDim.y;
    const int k0  = s * kc;

    const int tx = tid & 15;
    const int ty = tid >> 4;
    const int lr = tid >> 2;
    const int lk = (tid & 3) * 2;

    float acc[4][4];
#pragma unroll
    for (int i = 0; i < 4; i++)
#pragma unroll
        for (int j = 0; j < 4; j++) acc[i][j] = 0.0f;

    const int gn = bn + lr;
    const bool okW = gn < N;

    for (int kk = 0; kk < kc; kk += 8) {
        float2 av = *reinterpret_cast<const float2*>(&Ab[(size_t)lr * K + k0 + kk + lk]);
        float2 wv = make_float2(0.f, 0.f);
        if (okW)
            wv = *reinterpret_cast<const float2*>(&Wb[(size_t)gn * K + k0 + kk + lk]);
        As[lk][lr] = av.x;  As[lk + 1][lr] = av.y;
        Ws[lk][lr] = wv.x;  Ws[lk + 1][lr] = wv.y;
        __syncthreads();

#pragma unroll
        for (int k = 0; k < 8; k++) {
            float a[4], b[4];
#pragma unroll
            for (int i = 0; i < 4; i++) a[i] = As[k][ty * 4 + i];
#pragma unroll
            for (int j = 0; j < 4; j++) b[j] = Ws[k][tx * 4 + j];
#pragma unroll
            for (int i = 0; i < 4; i++)
#pragma unroll
                for (int j = 0; j < 4; j++)
                    acc[i][j] = fmaf(a[i], b[j], acc[i][j]);
        }
        __syncthreads();
    }

#pragma unroll
    for (int i = 0; i < 4; i++) {
        int m = ty * 4 + i;
#pragma unroll
        for (int j = 0; j < 4; j++) {
            int n = bn + tx * 4 + j;
            if (n < N)
                Pb[((size_t)s * 64 + m) * N + n] = acc[i][j];
        }
    }
}

template <int EPI>
__global__ void splitk_epi(int N, int nsplit,
                           const float* __restrict__ partial,
                           const float* __restrict__ bias,
                           const float* __restrict__ aU,
                           float* __restrict__ C,
                           float* __restrict__ O,
                           int l, int row_off,
                           size_t pStride, size_t bStride, size_t cStride)
{
    const float* Pb = partial + blockIdx.y * pStride;
    const float* Bb = bias + blockIdx.y * bStride;
    float* Cb = C ? C + blockIdx.y * cStride : nullptr;

    int idx = blockIdx.x * blockDim.x + threadIdx.x;
    if (idx >= 64 * N) return;
    int m = idx / N;
    int n = idx - m * N;
    float acc = 0.0f;
    for (int s = 0; s < nsplit; s++)
        acc += Pb[((size_t)s * 64 + m) * N + n];
    float v = acc + Bb[n];
    if (EPI == 0) {
        Cb[(size_t)m * N + n] = v;
    } else if (EPI == 1) {
        Cb[(size_t)m * N + n] = tanhf(v);
    } else if (EPI == 2) {
        v += aU[(size_t)m * N + n];
        v = tanhf(v);
        Cb[(size_t)m * N + n] = v;
        O[(((size_t)0 * LL + l) * BB + m) * HH + n] = v;
    } else { // EPI == 3
        O[(size_t)(m + row_off) * N + n] = v;
    }
}

// =======================================================================
// Big GEMM on tensor cores: fp16 mma.sync.m16n8k16 + ldmatrix,
// 3-stage cp.async pipeline, 128x256 block tile, 8 warps of 64x64.
// =======================================================================
#define CBM 128
#define CBN 256
#define CBK 32                        // halves per K-chunk (64 B data/row)
#define NSTG 3
#define HSTR 40                       // row stride in halves (80 B, conflict-free)
#define ABUF_BYTES (CBM * HSTR * 2)   // 10240
#define WBUF_BYTES (CBN * HSTR * 2)   // 20480
#define SMEM_BYTES (NSTG * (ABUF_BYTES + WBUF_BYTES))   // 92160

__device__ __forceinline__ void cp_async16(uint32_t saddr, const void* gptr, bool ok) {
    int sz = ok ? 16 : 0;
    asm volatile("cp.async.cg.shared.global [%0], [%1], 16, %2;\n"
                 :: "r"(saddr), "l"(gptr), "r"(sz));
}

__device__ __forceinline__ void mma_f16(float c[4], const unsigned a[4],
                                        unsigned b0, unsigned b1) {
    asm volatile("mma.sync.aligned.m16n8k16.row.col.f32.f16.f16.f32 "
                 "{%0,%1,%2,%3}, {%4,%5,%6,%7}, {%8,%9}, {%0,%1,%2,%3};"
                 : "+f"(c[0]), "+f"(c[1]), "+f"(c[2]), "+f"(c[3])
                 : "r"(a[0]), "r"(a[1]), "r"(a[2]), "r"(a[3]),
                   "r"(b0), "r"(b1));
}

__device__ __forceinline__ void ldsm_x4(unsigned r[4], uint32_t saddr) {
    asm volatile("ldmatrix.sync.aligned.m8n8.x4.shared.b16 {%0,%1,%2,%3}, [%4];"
                 : "=r"(r[0]), "=r"(r[1]), "=r"(r[2]), "=r"(r[3]) : "r"(saddr));
}

template <int EPI>
__global__ __launch_bounds__(256, 1)
void hgemm(int M, int N, int K,
           const __half* __restrict__ A,
           const __half* __restrict__ W,
           const float* __restrict__ bias,
           const float* __restrict__ aU,
           __half* __restrict__ C,
           float* __restrict__ O,
           int t0, int l, int row_off)
{
    extern __shared__ char smraw[];

    const int tid  = threadIdx.x;
    const int lane = tid & 31;
    const int wid  = tid >> 5;
    const int wm   = (wid & 1) * 64;
    const int wn   = (wid >> 1) * 64;
    const int grp  = lane >> 2;
    const int tig  = lane & 3;

    const int bm = blockIdx.x * CBM;
    const int bn = blockIdx.y * CBN;

    uint32_t sbase;
    asm("{ .reg .u64 t; cvta.to.shared.u64 t, %1; cvt.u32.u64 %0, t; }"
        : "=r"(sbase) : "l"(smraw));

    bool aok[2];  const __half* agp[2];  uint32_t asm_[2];
#pragma unroll
    for (int i = 0; i < 2; i++) {
        int slot = tid + 256 * i;
        int row = slot >> 2, seg = slot & 3;
        aok[i] = (bm + row) < M;
        agp[i] = A + (size_t)(aok[i] ? bm + row : 0) * K + seg * 8;
        asm_[i] = sbase + (uint32_t)(row * (HSTR * 2) + seg * 16);
    }
    bool wok[4];  const __half* wgp[4];  uint32_t wsm_[4];
#pragma unroll
    for (int i = 0; i < 4; i++) {
        int slot = tid + 256 * i;
        int row = slot >> 2, seg = slot & 3;
        wok[i] = (bn + row) < N;
        wgp[i] = W + (size_t)(wok[i] ? bn + row : 0) * K + seg * 8;
        wsm_[i] = sbase + (uint32_t)(NSTG * ABUF_BYTES + row * (HSTR * 2) + seg * 16);
    }

    const int lrow = lane & 15;
    const int lcol = lane >> 4;
    uint32_t aoff[4], boff[4];
#pragma unroll
    for (int mf = 0; mf < 4; mf++)
        aoff[mf] = (uint32_t)((wm + mf * 16 + lrow) * (HSTR * 2) + lcol * 16);
#pragma unroll
    for (int p = 0; p < 4; p++)
        boff[p] = (uint32_t)((wn + p * 16 + lrow) * (HSTR * 2) + lcol * 16);

    float acc[4][8][4];
#pragma unroll
    for (int mf = 0; mf < 4; mf++)
#pragma unroll
        for (int nf = 0; nf < 8; nf++)
#pragma unroll
            for (int r = 0; r < 4; r++) acc[mf][nf][r] = 0.0f;

    const int kT = K / CBK;

#pragma unroll
    for (int s = 0; s < NSTG - 1; s++) {
#pragma unroll
        for (int i = 0; i < 2; i++)
            cp_async16(asm_[i] + s * ABUF_BYTES, agp[i] + s * CBK, aok[i]);
#pragma unroll
        for (int i = 0; i < 4; i++)
            cp_async16(wsm_[i] + s * WBUF_BYTES, wgp[i] + s * CBK, wok[i]);
        asm volatile("cp.async.commit_group;\n");
    }

    for (int kt = 0; kt < kT; kt++) {
        asm volatile("cp.async.wait_group %0;\n" :: "n"(NSTG - 2));
        __syncthreads();

        const int pf = kt + NSTG - 1;
        if (pf < kT) {
            const int ps = pf % NSTG;
#pragma unroll
            for (int i = 0; i < 2; i++)
                cp_async16(asm_[i] + ps * ABUF_BYTES, agp[i] + pf * CBK, aok[i]);
#pragma unroll
            for (int i = 0; i < 4; i++)
                cp_async16(wsm_[i] + ps * WBUF_BYTES, wgp[i] + pf * CBK, wok[i]);
        }
        asm volatile("cp.async.commit_group;\n");

        const int cb = kt % NSTG;
        const uint32_t abase = sbase + cb * ABUF_BYTES;
        const uint32_t wbase = sbase + NSTG * ABUF_BYTES + cb * WBUF_BYTES;

#pragma unroll
        for (int ks = 0; ks < 2; ks++) {
            const uint32_t kb = ks * 32;
            unsigned af[4][4], bf[4][4];
#pragma unroll
            for (int mf = 0; mf < 4; mf++)
                ldsm_x4(af[mf], abase + aoff[mf] + kb);
#pragma unroll
            for (int p = 0; p < 4; p++)
                ldsm_x4(bf[p], wbase + boff[p] + kb);
#pragma unroll
            for (int mf = 0; mf < 4; mf++)
#pragma unroll
                for (int p = 0; p < 4; p++) {
                    mma_f16(acc[mf][2 * p],     af[mf], bf[p][0], bf[p][2]);
                    mma_f16(acc[mf][2 * p + 1], af[mf], bf[p][1], bf[p][3]);
                }
        }
    }

    // ---- epilogue ----
#pragma unroll
    for (int mf = 0; mf < 4; mf++) {
#pragma unroll
        for (int rh = 0; rh < 2; rh++) {
            int gm = bm + wm + mf * 16 + grp + rh * 8;
            if (gm >= M) continue;
#pragma unroll
            for (int nf = 0; nf < 8; nf++) {
                int gn = bn + wn + nf * 8 + tig * 2;
                if (gn >= N) continue;
                float v0 = acc[mf][nf][rh * 2 + 0] + bias[gn];
                float v1 = acc[mf][nf][rh * 2 + 1] + bias[gn + 1];
                if (EPI == 1) {
                    v0 = tanhf(v0); v1 = tanhf(v1);
                    __half2 h = __floats2half2_rn(v0, v1);
                    *reinterpret_cast<__half2*>(&C[(size_t)gm * N + gn]) = h;
                } else if (EPI == 2) {
                    const float2 au = *reinterpret_cast<const float2*>(
                        &aU[(size_t)(gm & 63) * N + gn]);
                    v0 = tanhf(v0 + au.x);
                    v1 = tanhf(v1 + au.y);
                    __half2 h = __floats2half2_rn(v0, v1);
                    *reinterpret_cast<__half2*>(&C[(size_t)gm * N + gn]) = h;
                    int t = t0 + (gm >> 6);
                    int b = gm & 63;
                    *reinterpret_cast<float2*>(
                        &O[(((size_t)t * LL + l) * BB + b) * HH + gn]) =
                        make_float2(v0, v1);
                } else { // EPI == 3
                    *reinterpret_cast<float2*>(&O[(size_t)(gm + row_off) * N + gn]) =
                        make_float2(v0, v1);
                }
            }
        }
    }
}

// ---------------- host-side orchestration -----------------------------------
static inline dim3 hgrid(int M, int N) {
    return dim3((M + CBM - 1) / CBM, (N + CBN - 1) / CBN);
}

template <int EPI>
static void small_gemm(int N, int K, int nsplit,
                       const float* A, const float* W, const float* bias,
                       const float* aU, float* C, float* O,
                       int l, int row_off, float* part, cudaStream_t st)
{
    dim3 g((N + 63) / 64, nsplit, 1);
    sgemm_splitk<<<g, 256, 0, st>>>(N, K, A, W, part, 0, 0, 0);
    int total = 64 * N;
    splitk_epi<EPI><<<dim3((total + 255) / 256, 1), 256, 0, st>>>(
        N, nsplit, part, bias, aU, C, O, l, row_off, 0, 0, 0);
}

static void small_gemm_pair(int N, int K, int nsplit,
                            const float* A, size_t aStr,
                            const float* W, size_t wStr,
                            const float* bias, size_t bStr,
                            float* C, size_t cStr, float* part, cudaStream_t st)
{
    size_t pStr = (size_t)nsplit * 64 * N;
    dim3 g((N + 63) / 64, nsplit, 2);
    sgemm_splitk<<<g, 256, 0, st>>>(N, K, A, W, part, aStr, wStr, pStr);
    int total = 64 * N;
    splitk_epi<0><<<dim3((total + 255) / 256, 2), 256, 0, st>>>(
        N, nsplit, part, bias, nullptr, C, nullptr, 0, 0, pStr, bStr, cStr);
}

extern "C" void kernel_launch(void* const* d_in, const int* in_sizes, int n_in,
                              void* d_out, int out_size)
{
    (void)in_sizes; (void)n_in; (void)out_size;
    const int*   inputs = (const int*)  d_in[0];
    const float* hidden = (const float*)d_in[1];   // (L,B,H)
    const float* emb    = (const float*)d_in[2];   // (V,E)
    const float* Ww     = (const float*)d_in[3];   // (L,H,E)
    const float* Wb     = (const float*)d_in[4];   // (L,H)
    const float* Uw     = (const float*)d_in[5];   // (L,H,H)
    const float* Ub     = (const float*)d_in[6];   // (L,H)
    const float* Fw     = (const float*)d_in[7];   // (L,E,H)
    const float* Fb     = (const float*)d_in[8];   // (L,E)
    const float* Dw     = (const float*)d_in[9];   // (V,H)
    const float* Db     = (const float*)d_in[10];  // (V,)

    float* out  = (float*)d_out;
    float* hall = out + (size_t)TT * BB * VV;      // h_all after logits

    __half *bufA, *bufB, *WwH, *FwH, *DwH;
    float *x0, *xt, *xt2, *h0, *aU, *part;
    cudaGetSymbolAddress((void**)&bufA, g_bufA);
    cudaGetSymbolAddress((void**)&bufB, g_bufB);
    cudaGetSymbolAddress((void**)&x0,  g_x0);
    cudaGetSymbolAddress((void**)&xt,  g_xt);
    cudaGetSymbolAddress((void**)&xt2, g_xt2);
    cudaGetSymbolAddress((void**)&h0,  g_h0);
    cudaGetSymbolAddress((void**)&aU,  g_aU);
    cudaGetSymbolAddress((void**)&part, g_part);
    cudaGetSymbolAddress((void**)&WwH, g_WwH);
    cudaGetSymbolAddress((void**)&FwH, g_FwH);
    cudaGetSymbolAddress((void**)&DwH, g_DwH);

    float* h00 = h0;
    float* h01 = h0 + (size_t)BB * HH;
    float* aU0 = aU;
    float* aU1 = aU + (size_t)BB * HH;

    cudaFuncSetAttribute(hgemm<1>, cudaFuncAttributeMaxDynamicSharedMemorySize, SMEM_BYTES);
    cudaFuncSetAttribute(hgemm<2>, cudaFuncAttributeMaxDynamicSharedMemorySize, SMEM_BYTES);
    cudaFuncSetAttribute(hgemm<3>, cudaFuncAttributeMaxDynamicSharedMemorySize, SMEM_BYTES);

    const size_t Wstride = (size_t)HH * EE;
    const size_t BH = (size_t)BB * HH;

    // lazy-init fork stream + events once (no device memory; work per call
    // is identical every call — determinism preserved)
    static cudaStream_t s2 = nullptr;
    static cudaEvent_t evFork = nullptr, evAU0 = nullptr, evAU1 = nullptr,
                       evJoin = nullptr;
    if (s2 == nullptr) {
        cudaStreamCreateWithFlags(&s2, cudaStreamNonBlocking);
        cudaEventCreateWithFlags(&evFork, cudaEventDisableTiming);
        cudaEventCreateWithFlags(&evAU0,  cudaEventDisableTiming);
        cudaEventCreateWithFlags(&evAU1,  cudaEventDisableTiming);
        cudaEventCreateWithFlags(&evJoin, cudaEventDisableTiming);
    }

    // ---- fork: stream2 does weight conversion + Phase-B gather ----
    cudaEventRecord(evFork, 0);
    cudaStreamWaitEvent(s2, evFork, 0);
    {
        int n4;
        n4 = (LL * HH * EE) / 4;
        f2h_kernel<<<(n4 + 255) / 256, 256, 0, s2>>>(Ww, WwH, n4);
        n4 = (LL * EE * HH) / 4;
        f2h_kernel<<<(n4 + 255) / 256, 256, 0, s2>>>(Fw, FwH, n4);
        n4 = (VV * HH) / 4;
        f2h_kernel<<<(n4 + 255) / 256, 256, 0, s2>>>(Dw, DwH, n4);
        gather_emb_h<<<(MREST * 256 + 255) / 256, 256, 0, s2>>>(inputs, emb, bufA,
                                                                BB, MREST);
    }

    // ---- Phase A on stream 0 ----
    gather_emb_f<<<(BB * 256 + 255) / 256, 256>>>(inputs, emb, x0, 0, BB);

    // aU-init pair (both layers, from initial hidden)
    small_gemm_pair(HH, HH, 32, hidden, BH, Uw, Wstride, Ub, HH, aU, BH, part, 0);
    // h00 = tanh(x0 @ Ww0^T + Wb0 + aU0_init)  [also h_all t=0,l=0]
    small_gemm<2>(HH, EE, 32, x0, Ww, Wb, aU0, h00, hall, 0, 0, part, 0);
    // aU0-final = h00 @ Uw0^T + Ub0  (gates Phase-B layer 0)
    small_gemm<0>(HH, HH, 32, h00, Uw, Ub, nullptr, aU0, nullptr, 0, 0, part, 0);
    cudaEventRecord(evAU0, 0);
    cudaStreamWaitEvent(s2, evAU0, 0);

    // ---- Phase B layer 0 on stream2 (overlaps rest of Phase A) ----
    hgemm<2><<<hgrid(MREST, HH), 256, SMEM_BYTES, s2>>>(MREST, HH, EE, bufA, WwH, Wb,
                                                        aU0, bufB, hall, 1, 0, 0);
    hgemm<1><<<hgrid(MREST, EE), 256, SMEM_BYTES, s2>>>(MREST, EE, HH, bufB, FwH, Fb,
                                                        nullptr, bufA, nullptr, 0, 0, 0);

    // ---- Phase A continues on stream 0 ----
    // xt = tanh(h00 @ Fw0^T + Fb0)
    small_gemm<1>(EE, HH, 32, h00, Fw, Fb, nullptr, xt, nullptr, 0, 0, part, 0);
    // h01 = tanh(xt @ Ww1^T + Wb1 + aU1_init)  [also h_all t=0,l=1]
    small_gemm<2>(HH, EE, 32, xt, Ww + Wstride, Wb + HH, aU1, h01, hall, 1, 0, part, 0);
    // aU1-final = h01 @ Uw1^T + Ub1  (gates Phase-B layer 1)
    small_gemm<0>(HH, HH, 32, h01, Uw + Wstride, Ub + HH, nullptr, aU1, nullptr,
                  0, 0, part, 0);
    cudaEventRecord(evAU1, 0);
    cudaStreamWaitEvent(s2, evAU1, 0);

    // ---- Phase B layer 1 + logits on stream2 ----
    hgemm<2><<<hgrid(MREST, HH), 256, SMEM_BYTES, s2>>>(MREST, HH, EE, bufA,
                                                        WwH + Wstride, Wb + HH,
                                                        aU1, bufB, hall, 1, 1, 0);
    hgemm<1><<<hgrid(MREST, EE), 256, SMEM_BYTES, s2>>>(MREST, EE, HH, bufB,
                                                        FwH + Wstride, Fb + EE,
                                                        nullptr, bufA, nullptr, 0, 0, 0);
    hgemm<3><<<hgrid(MREST, VV), 256, SMEM_BYTES, s2>>>(MREST, VV, HH, bufA, DwH, Db,
                                                        nullptr, nullptr, out, 0, 0, BB);

    // ---- Phase A tail on stream 0 (t=0 logits path) ----
    // xt2 = tanh(h01 @ Fw1^T + Fb1)
    small_gemm<1>(EE, HH, 32, h01, Fw + Wstride, Fb + EE, nullptr, xt2, nullptr,
                  0, 0, part, 0);
    // logits[0] = xt2 @ Dw^T + Db  (rows 0..63 of out)
    small_gemm<3>(VV, HH, 8, xt2, Dw, Db, nullptr, nullptr, out, 0, 0, part, 0);

    // ---- join ----
    cudaEventRecord(evJoin, s2);
    cudaStreamWaitEvent(0, evJoin, 0);
}

// round 13
// speedup vs baseline: 1.2433x; 1.0273x over previous
#include <cuda_runtime.h>
#include <cuda_fp16.h>
#include <cstddef>
#include <cstdint>

// Problem constants (fixed by the dataset)
#define TT 128
#define BB 64
#define EE 1024
#define HH 1024
#define VV 10000
#define LL 2

#define MREST (127 * 64)   // 8128 rows for t = 1..127

// ---------------- scratch (device globals; no allocations allowed) ----------
__device__ __align__(256) __half g_bufA[MREST * 1024];
__device__ __align__(256) __half g_bufB[MREST * 1024];
__device__ __align__(256) float  g_raw [MREST * 1024];  // raw L0 accumulators
__device__ float g_x0 [BB * EE];
__device__ float g_xt [BB * EE];
__device__ float g_xt2[BB * EE];
__device__ float g_h0 [2 * BB * HH];           // h00 | h01
__device__ float g_aU [2 * BB * HH];           // aU0 | aU1
__device__ float g_part[8 * 64 * 10016];       // split-K partials
__device__ __align__(256) __half g_WwH[LL * HH * EE];   // fp16 weights
__device__ __align__(256) __half g_FwH[LL * EE * HH];
__device__ __align__(256) __half g_DwH[VV * HH];

// ---------------- fp32 -> fp16 weight conversion ----------------------------
__global__ void f2h_kernel(const float* __restrict__ src,
                           __half* __restrict__ dst, int n4)
{
    int i = blockIdx.x * blockDim.x + threadIdx.x;
    if (i >= n4) return;
    float4 v = reinterpret_cast<const float4*>(src)[i];
    __half2 lo = __floats2half2_rn(v.x, v.y);
    __half2 hi = __floats2half2_rn(v.z, v.w);
    uint2 o;
    o.x = *reinterpret_cast<unsigned*>(&lo);
    o.y = *reinterpret_cast<unsigned*>(&hi);
    reinterpret_cast<uint2*>(dst)[i] = o;
}

// ---------------- embedding gathers ------------------------------------------
__global__ void gather_emb_f(const int* __restrict__ inputs,
                             const float* __restrict__ emb,
                             float* __restrict__ X,
                             int ioff, int nrows)
{
    int idx = blockIdx.x * blockDim.x + threadIdx.x;
    int total = nrows * 256;
    if (idx >= total) return;
    int r = idx >> 8;
    int c = idx & 255;
    int tok = inputs[r + ioff];
    reinterpret_cast<float4*>(X)[(size_t)r * 256 + c] =
        reinterpret_cast<const float4*>(emb)[(size_t)tok * 256 + c];
}

__global__ void gather_emb_h(const int* __restrict__ inputs,
                             const float* __restrict__ emb,
                             __half* __restrict__ X,
                             int ioff, int nrows)
{
    int idx = blockIdx.x * blockDim.x + threadIdx.x;
    int total = nrows * 256;
    if (idx >= total) return;
    int r = idx >> 8;
    int c = idx & 255;
    int tok = inputs[r + ioff];
    float4 v = reinterpret_cast<const float4*>(emb)[(size_t)tok * 256 + c];
    __half2 lo = __floats2half2_rn(v.x, v.y);
    __half2 hi = __floats2half2_rn(v.z, v.w);
    uint2 o;
    o.x = *reinterpret_cast<unsigned*>(&lo);
    o.y = *reinterpret_cast<unsigned*>(&hi);
    reinterpret_cast<uint2*>(X)[(size_t)r * 256 + c] = o;
}

// ---------------- deferred aU epilogue for Phase-B layer 0 -------------------
// X1h = half(tanh((raw + Wb) + aU[b]));  hall[t,l=0,b,:] = tanh(...)
__global__ void aU_epi(const float* __restrict__ raw,
                       const float* __restrict__ Wb,
                       const float* __restrict__ aU,
                       __half* __restrict__ Xout,
                       float* __restrict__ hall, int l)
{
    int idx = blockIdx.x * blockDim.x + threadIdx.x;   // over MREST*256 float4
    if (idx >= MREST * 256) return;
    int m = idx >> 8;
    int c = idx & 255;
    int n = c * 4;

    float4 v  = reinterpret_cast<const float4*>(raw)[(size_t)m * 256 + c];
    float4 b  = *reinterpret_cast<const float4*>(&Wb[n]);
    float4 au = *reinterpret_cast<const float4*>(&aU[(size_t)(m & 63) * HH + n]);
    float v0 = tanhf((v.x + b.x) + au.x);
    float v1 = tanhf((v.y + b.y) + au.y);
    float v2 = tanhf((v.z + b.z) + au.z);
    float v3 = tanhf((v.w + b.w) + au.w);

    __half2 lo = __floats2half2_rn(v0, v1);
    __half2 hi = __floats2half2_rn(v2, v3);
    uint2 o;
    o.x = *reinterpret_cast<unsigned*>(&lo);
    o.y = *reinterpret_cast<unsigned*>(&hi);
    reinterpret_cast<uint2*>(Xout)[(size_t)m * 256 + c] = o;

    int t = 1 + (m >> 6);
    int bb = m & 63;
    *reinterpret_cast<float4*>(&hall[(((size_t)t * LL + l) * BB + bb) * HH + n]) =
        make_float4(v0, v1, v2, v3);
}

// =======================================================================
// Small-M (M=64) split-K fp32 GEMM (Phase A), batchable via grid.z
// =======================================================================
__global__ __launch_bounds__(256)
void sgemm_splitk(int N, int K,
                  const float* __restrict__ A,
                  const float* __restrict__ W,
                  float* __restrict__ partial,
                  size_t aStride, size_t wStride, size_t pStride)
{
    const float* Ab = A + blockIdx.z * aStride;
    const float* Wb = W + blockIdx.z * wStride;
    float* Pb = partial + blockIdx.z * pStride;

    __shared__ float As[8][68];
    __shared__ float Ws[8][68];

    const int tid = threadIdx.x;
    const int bn  = blockIdx.x * 64;
    const int s   = blockIdx.y;
    const int kc  = K / gridDim.y;
    const int k0  = s * kc;

    const int tx = tid & 15;
    const int ty = tid >> 4;
    const int lr = tid >> 2;
    const int lk = (tid & 3) * 2;

    float acc[4][4];
#pragma unroll
    for (int i = 0; i < 4; i++)
#pragma unroll
        for (int j = 0; j < 4; j++) acc[i][j] = 0.0f;

    const int gn = bn + lr;
    const bool okW = gn < N;

    for (int kk = 0; kk < kc; kk += 8) {
        float2 av = *reinterpret_cast<const float2*>(&Ab[(size_t)lr * K + k0 + kk + lk]);
        float2 wv = make_float2(0.f, 0.f);
        if (okW)
            wv = *reinterpret_cast<const float2*>(&Wb[(size_t)gn * K + k0 + kk + lk]);
        As[lk][lr] = av.x;  As[lk + 1][lr] = av.y;
        Ws[lk][lr] = wv.x;  Ws[lk + 1][lr] = wv.y;
        __syncthreads();

#pragma unroll
        for (int k = 0; k < 8; k++) {
            float a[4], b[4];
#pragma unroll
            for (int i = 0; i < 4; i++) a[i] = As[k][ty * 4 + i];
#pragma unroll
            for (int j = 0; j < 4; j++) b[j] = Ws[k][tx * 4 + j];
#pragma unroll
            for (int i = 0; i < 4; i++)
#pragma unroll
                for (int j = 0; j < 4; j++)
                    acc[i][j] = fmaf(a[i], b[j], acc[i][j]);
        }
        __syncthreads();
    }

#pragma unroll
    for (int i = 0; i < 4; i++) {
        int m = ty * 4 + i;
#pragma unroll
        for (int j = 0; j < 4; j++) {
            int n = bn + tx * 4 + j;
            if (n < N)
                Pb[((size_t)s * 64 + m) * N + n] = acc[i][j];
        }
    }
}

template <int EPI>
__global__ void splitk_epi(int N, int nsplit,
                           const float* __restrict__ partial,
                           const float* __restrict__ bias,
                           const float* __restrict__ aU,
                           float* __restrict__ C,
                           float* __restrict__ O,
                           int l, int row_off,
                           size_t pStride, size_t bStride, size_t cStride)
{
    const float* Pb = partial + blockIdx.y * pStride;
    const float* Bb = bias + blockIdx.y * bStride;
    float* Cb = C ? C + blockIdx.y * cStride : nullptr;

    int idx = blockIdx.x * blockDim.x + threadIdx.x;
    if (idx >= 64 * N) return;
    int m = idx / N;
    int n = idx - m * N;
    float acc = 0.0f;
    for (int s = 0; s < nsplit; s++)
        acc += Pb[((size_t)s * 64 + m) * N + n];
    float v = acc + Bb[n];
    if (EPI == 0) {
        Cb[(size_t)m * N + n] = v;
    } else if (EPI == 1) {
        Cb[(size_t)m * N + n] = tanhf(v);
    } else if (EPI == 2) {
        v += aU[(size_t)m * N + n];
        v = tanhf(v);
        Cb[(size_t)m * N + n] = v;
        O[(((size_t)0 * LL + l) * BB + m) * HH + n] = v;
    } else { // EPI == 3
        O[(size_t)(m + row_off) * N + n] = v;
    }
}

// =======================================================================
// Big GEMM on tensor cores: fp16 mma.sync.m16n8k16 + ldmatrix,
// 3-stage cp.async pipeline, 128x256 block tile, 8 warps of 64x64.
// EPI 0: O_raw[gm*N+gn] = acc (fp32, no bias) — for deferred epilogue.
// =======================================================================
#define CBM 128
#define CBN 256
#define CBK 32
#define NSTG 3
#define HSTR 40
#define ABUF_BYTES (CBM * HSTR * 2)
#define WBUF_BYTES (CBN * HSTR * 2)
#define SMEM_BYTES (NSTG * (ABUF_BYTES + WBUF_BYTES))

__device__ __forceinline__ void cp_async16(uint32_t saddr, const void* gptr, bool ok) {
    int sz = ok ? 16 : 0;
    asm volatile("cp.async.cg.shared.global [%0], [%1], 16, %2;\n"
                 :: "r"(saddr), "l"(gptr), "r"(sz));
}

__device__ __forceinline__ void mma_f16(float c[4], const unsigned a[4],
                                        unsigned b0, unsigned b1) {
    asm volatile("mma.sync.aligned.m16n8k16.row.col.f32.f16.f16.f32 "
                 "{%0,%1,%2,%3}, {%4,%5,%6,%7}, {%8,%9}, {%0,%1,%2,%3};"
                 : "+f"(c[0]), "+f"(c[1]), "+f"(c[2]), "+f"(c[3])
                 : "r"(a[0]), "r"(a[1]), "r"(a[2]), "r"(a[3]),
                   "r"(b0), "r"(b1));
}

__device__ __forceinline__ void ldsm_x4(unsigned r[4], uint32_t saddr) {
    asm volatile("ldmatrix.sync.aligned.m8n8.x4.shared.b16 {%0,%1,%2,%3}, [%4];"
                 : "=r"(r[0]), "=r"(r[1]), "=r"(r[2]), "=r"(r[3]) : "r"(saddr));
}

template <int EPI>
__global__ __launch_bounds__(256, 1)
void hgemm(int M, int N, int K,
           const __half* __restrict__ A,
           const __half* __restrict__ W,
           const float* __restrict__ bias,
           const float* __restrict__ aU,
           __half* __restrict__ C,
           float* __restrict__ O,
           int t0, int l, int row_off)
{
    extern __shared__ char smraw[];

    const int tid  = threadIdx.x;
    const int lane = tid & 31;
    const int wid  = tid >> 5;
    const int wm   = (wid & 1) * 64;
    const int wn   = (wid >> 1) * 64;
    const int grp  = lane >> 2;
    const int tig  = lane & 3;

    const int bm = blockIdx.x * CBM;
    const int bn = blockIdx.y * CBN;

    uint32_t sbase;
    asm("{ .reg .u64 t; cvta.to.shared.u64 t, %1; cvt.u32.u64 %0, t; }"
        : "=r"(sbase) : "l"(smraw));

    bool aok[2];  const __half* agp[2];  uint32_t asm_[2];
#pragma unroll
    for (int i = 0; i < 2; i++) {
        int slot = tid + 256 * i;
        int row = slot >> 2, seg = slot & 3;
        aok[i] = (bm + row) < M;
        agp[i] = A + (size_t)(aok[i] ? bm + row : 0) * K + seg * 8;
        asm_[i] = sbase + (uint32_t)(row * (HSTR * 2) + seg * 16);
    }
    bool wok[4];  const __half* wgp[4];  uint32_t wsm_[4];
#pragma unroll
    for (int i = 0; i < 4; i++) {
        int slot = tid + 256 * i;
        int row = slot >> 2, seg = slot & 3;
        wok[i] = (bn + row) < N;
        wgp[i] = W + (size_t)(wok[i] ? bn + row : 0) * K + seg * 8;
        wsm_[i] = sbase + (uint32_t)(NSTG * ABUF_BYTES + row * (HSTR * 2) + seg * 16);
    }

    const int lrow = lane & 15;
    const int lcol = lane >> 4;
    uint32_t aoff[4], boff[4];
#pragma unroll
    for (int mf = 0; mf < 4; mf++)
        aoff[mf] = (uint32_t)((wm + mf * 16 + lrow) * (HSTR * 2) + lcol * 16);
#pragma unroll
    for (int p = 0; p < 4; p++)
        boff[p] = (uint32_t)((wn + p * 16 + lrow) * (HSTR * 2) + lcol * 16);

    float acc[4][8][4];
#pragma unroll
    for (int mf = 0; mf < 4; mf++)
#pragma unroll
        for (int nf = 0; nf < 8; nf++)
#pragma unroll
            for (int r = 0; r < 4; r++) acc[mf][nf][r] = 0.0f;

    const int kT = K / CBK;

#pragma unroll
    for (int s = 0; s < NSTG - 1; s++) {
#pragma unroll
        for (int i = 0; i < 2; i++)
            cp_async16(asm_[i] + s * ABUF_BYTES, agp[i] + s * CBK, aok[i]);
#pragma unroll
        for (int i = 0; i < 4; i++)
            cp_async16(wsm_[i] + s * WBUF_BYTES, wgp[i] + s * CBK, wok[i]);
        asm volatile("cp.async.commit_group;\n");
    }

    for (int kt = 0; kt < kT; kt++) {
        asm volatile("cp.async.wait_group %0;\n" :: "n"(NSTG - 2));
        __syncthreads();

        const int pf = kt + NSTG - 1;
        if (pf < kT) {
            const int ps = pf % NSTG;
#pragma unroll
            for (int i = 0; i < 2; i++)
                cp_async16(asm_[i] + ps * ABUF_BYTES, agp[i] + pf * CBK, aok[i]);
#pragma unroll
            for (int i = 0; i < 4; i++)
                cp_async16(wsm_[i] + ps * WBUF_BYTES, wgp[i] + pf * CBK, wok[i]);
        }
        asm volatile("cp.async.commit_group;\n");

        const int cb = kt % NSTG;
        const uint32_t abase = sbase + cb * ABUF_BYTES;
        const uint32_t wbase = sbase + NSTG * ABUF_BYTES + cb * WBUF_BYTES;

#pragma unroll
        for (int ks = 0; ks < 2; ks++) {
            const uint32_t kb = ks * 32;
            unsigned af[4][4], bf[4][4];
#pragma unroll
            for (int mf = 0; mf < 4; mf++)
                ldsm_x4(af[mf], abase + aoff[mf] + kb);
#pragma unroll
            for (int p = 0; p < 4; p++)
                ldsm_x4(bf[p], wbase + boff[p] + kb);
#pragma unroll
            for (int mf = 0; mf < 4; mf++)
#pragma unroll
                for (int p = 0; p < 4; p++) {
                    mma_f16(acc[mf][2 * p],     af[mf], bf[p][0], bf[p][2]);
                    mma_f16(acc[mf][2 * p + 1], af[mf], bf[p][1], bf[p][3]);
                }
        }
    }

    // ---- epilogue ----
#pragma unroll
    for (int mf = 0; mf < 4; mf++) {
#pragma unroll
        for (int rh = 0; rh < 2; rh++) {
            int gm = bm + wm + mf * 16 + grp + rh * 8;
            if (gm >= M) continue;
#pragma unroll
            for (int nf = 0; nf < 8; nf++) {
                int gn = bn + wn + nf * 8 + tig * 2;
                if (gn >= N) continue;
                if (EPI == 0) {   // raw accumulator dump
                    *reinterpret_cast<float2*>(&O[(size_t)gm * N + gn]) =
                        make_float2(acc[mf][nf][rh * 2 + 0], acc[mf][nf][rh * 2 + 1]);
                    continue;
                }
                float v0 = acc[mf][nf][rh * 2 + 0] + bias[gn];
                float v1 = acc[mf][nf][rh * 2 + 1] + bias[gn + 1];
                if (EPI == 1) {
                    v0 = tanhf(v0); v1 = tanhf(v1);
                    __half2 h = __floats2half2_rn(v0, v1);
                    *reinterpret_cast<__half2*>(&C[(size_t)gm * N + gn]) = h;
                } else if (EPI == 2) {
                    const float2 au = *reinterpret_cast<const float2*>(
                        &aU[(size_t)(gm & 63) * N + gn]);
                    v0 = tanhf(v0 + au.x);
                    v1 = tanhf(v1 + au.y);
                    __half2 h = __floats2half2_rn(v0, v1);
                    *reinterpret_cast<__half2*>(&C[(size_t)gm * N + gn]) = h;
                    int t = t0 + (gm >> 6);
                    int b = gm & 63;
                    *reinterpret_cast<float2*>(
                        &O[(((size_t)t * LL + l) * BB + b) * HH + gn]) =
                        make_float2(v0, v1);
                } else { // EPI == 3
                    *reinterpret_cast<float2*>(&O[(size_t)(gm + row_off) * N + gn]) =
                        make_float2(v0, v1);
                }
            }
        }
    }
}

// ---------------- host-side orchestration -----------------------------------
static inline dim3 hgrid(int M, int N) {
    return dim3((M + CBM - 1) / CBM, (N + CBN - 1) / CBN);
}

template <int EPI>
static void small_gemm(int N, int K, int nsplit,
                       const float* A, const float* W, const float* bias,
                       const float* aU, float* C, float* O,
                       int l, int row_off, float* part, cudaStream_t st)
{
    dim3 g((N + 63) / 64, nsplit, 1);
    sgemm_splitk<<<g, 256, 0, st>>>(N, K, A, W, part, 0, 0, 0);
    int total = 64 * N;
    splitk_epi<EPI><<<dim3((total + 255) / 256, 1), 256, 0, st>>>(
        N, nsplit, part, bias, aU, C, O, l, row_off, 0, 0, 0);
}

static void small_gemm_pair(int N, int K, int nsplit,
                            const float* A, size_t aStr,
                            const float* W, size_t wStr,
                            const float* bias, size_t bStr,
                            float* C, size_t cStr, float* part, cudaStream_t st)
{
    size_t pStr = (size_t)nsplit * 64 * N;
    dim3 g((N + 63) / 64, nsplit, 2);
    sgemm_splitk<<<g, 256, 0, st>>>(N, K, A, W, part, aStr, wStr, pStr);
    int total = 64 * N;
    splitk_epi<0><<<dim3((total + 255) / 256, 2), 256, 0, st>>>(
        N, nsplit, part, bias, nullptr, C, nullptr, 0, 0, pStr, bStr, cStr);
}

extern "C" void kernel_launch(void* const* d_in, const int* in_sizes, int n_in,
                              void* d_out, int out_size)
{
    (void)in_sizes; (void)n_in; (void)out_size;
    const int*   inputs = (const int*)  d_in[0];
    const float* hidden = (const float*)d_in[1];   // (L,B,H)
    const float* emb    = (const float*)d_in[2];   // (V,E)
    const float* Ww     = (const float*)d_in[3];   // (L,H,E)
    const float* Wb     = (const float*)d_in[4];   // (L,H)
    const float* Uw     = (const float*)d_in[5];   // (L,H,H)
    const float* Ub     = (const float*)d_in[6];   // (L,H)
    const float* Fw     = (const float*)d_in[7];   // (L,E,H)
    const float* Fb     = (const float*)d_in[8];   // (L,E)
    const float* Dw     = (const float*)d_in[9];   // (V,H)
    const float* Db     = (const float*)d_in[10];  // (V,)

    float* out  = (float*)d_out;
    float* hall = out + (size_t)TT * BB * VV;      // h_all after logits

    __half *bufA, *bufB, *WwH, *FwH, *DwH;
    float *x0, *xt, *xt2, *h0, *aU, *part, *raw;
    cudaGetSymbolAddress((void**)&bufA, g_bufA);
    cudaGetSymbolAddress((void**)&bufB, g_bufB);
    cudaGetSymbolAddress((void**)&raw,  g_raw);
    cudaGetSymbolAddress((void**)&x0,  g_x0);
    cudaGetSymbolAddress((void**)&xt,  g_xt);
    cudaGetSymbolAddress((void**)&xt2, g_xt2);
    cudaGetSymbolAddress((void**)&h0,  g_h0);
    cudaGetSymbolAddress((void**)&aU,  g_aU);
    cudaGetSymbolAddress((void**)&part, g_part);
    cudaGetSymbolAddress((void**)&WwH, g_WwH);
    cudaGetSymbolAddress((void**)&FwH, g_FwH);
    cudaGetSymbolAddress((void**)&DwH, g_DwH);

    float* h00 = h0;
    float* h01 = h0 + (size_t)BB * HH;
    float* aU0 = aU;
    float* aU1 = aU + (size_t)BB * HH;

    cudaFuncSetAttribute(hgemm<0>, cudaFuncAttributeMaxDynamicSharedMemorySize, SMEM_BYTES);
    cudaFuncSetAttribute(hgemm<1>, cudaFuncAttributeMaxDynamicSharedMemorySize, SMEM_BYTES);
    cudaFuncSetAttribute(hgemm<2>, cudaFuncAttributeMaxDynamicSharedMemorySize, SMEM_BYTES);
    cudaFuncSetAttribute(hgemm<3>, cudaFuncAttributeMaxDynamicSharedMemorySize, SMEM_BYTES);

    const size_t Wstride = (size_t)HH * EE;
    const size_t BH = (size_t)BB * HH;

    static cudaStream_t s2 = nullptr;
    static cudaEvent_t evFork = nullptr, evAU0 = nullptr, evAU1 = nullptr,
                       evJoin = nullptr;
    if (s2 == nullptr) {
        cudaStreamCreateWithFlags(&s2, cudaStreamNonBlocking);
        cudaEventCreateWithFlags(&evFork, cudaEventDisableTiming);
        cudaEventCreateWithFlags(&evAU0,  cudaEventDisableTiming);
        cudaEventCreateWithFlags(&evAU1,  cudaEventDisableTiming);
        cudaEventCreateWithFlags(&evJoin, cudaEventDisableTiming);
    }

    // ---- fork: stream2 does conversion + gather + L0 mainloop ----
    cudaEventRecord(evFork, 0);
    cudaStreamWaitEvent(s2, evFork, 0);
    {
        int n4;
        n4 = (LL * HH * EE) / 4;
        f2h_kernel<<<(n4 + 255) / 256, 256, 0, s2>>>(Ww, WwH, n4);
        n4 = (LL * EE * HH) / 4;
        f2h_kernel<<<(n4 + 255) / 256, 256, 0, s2>>>(Fw, FwH, n4);
        n4 = (VV * HH) / 4;
        f2h_kernel<<<(n4 + 255) / 256, 256, 0, s2>>>(Dw, DwH, n4);
        gather_emb_h<<<(MREST * 256 + 255) / 256, 256, 0, s2>>>(inputs, emb, bufA,
                                                                BB, MREST);
    }
    // L0 mainloop: raw = X @ Ww0^T (no aU dependency!)
    hgemm<0><<<hgrid(MREST, HH), 256, SMEM_BYTES, s2>>>(MREST, HH, EE, bufA, WwH,
                                                        nullptr, nullptr, nullptr,
                                                        raw, 0, 0, 0);

    // ---- Phase A on stream 0 (now fully hidden under L0 mainloop) ----
    gather_emb_f<<<(BB * 256 + 255) / 256, 256>>>(inputs, emb, x0, 0, BB);
    small_gemm_pair(HH, HH, 32, hidden, BH, Uw, Wstride, Ub, HH, aU, BH, part, 0);
    small_gemm<2>(HH, EE, 32, x0, Ww, Wb, aU0, h00, hall, 0, 0, part, 0);
    small_gemm<0>(HH, HH, 32, h00, Uw, Ub, nullptr, aU0, nullptr, 0, 0, part, 0);
    cudaEventRecord(evAU0, 0);
    cudaStreamWaitEvent(s2, evAU0, 0);

    // ---- deferred L0 epilogue + rest of layer 0 on stream2 ----
    aU_epi<<<(MREST * 256 + 255) / 256, 256, 0, s2>>>(raw, Wb, aU0, bufB, hall, 0);
    hgemm<1><<<hgrid(MREST, EE), 256, SMEM_BYTES, s2>>>(MREST, EE, HH, bufB, FwH, Fb,
                                                        nullptr, bufA, nullptr, 0, 0, 0);

    // ---- Phase A continues on stream 0 ----
    small_gemm<1>(EE, HH, 32, h00, Fw, Fb, nullptr, xt, nullptr, 0, 0, part, 0);
    small_gemm<2>(HH, EE, 32, xt, Ww + Wstride, Wb + HH, aU1, h01, hall, 1, 0, part, 0);
    small_gemm<0>(HH, HH, 32, h01, Uw + Wstride, Ub + HH, nullptr, aU1, nullptr,
                  0, 0, part, 0);
    cudaEventRecord(evAU1, 0);
    cudaStreamWaitEvent(s2, evAU1, 0);

    // ---- Phase B layer 1 + logits on stream2 ----
    hgemm<2><<<hgrid(MREST, HH), 256, SMEM_BYTES, s2>>>(MREST, HH, EE, bufA,
                                                        WwH + Wstride, Wb + HH,
                                                        aU1, bufB, hall, 1, 1, 0);
    hgemm<1><<<hgrid(MREST, EE), 256, SMEM_BYTES, s2>>>(MREST, EE, HH, bufB,
                                                        FwH + Wstride, Fb + EE,
                                                        nullptr, bufA, nullptr, 0, 0, 0);
    hgemm<3><<<hgrid(MREST, VV), 256, SMEM_BYTES, s2>>>(MREST, VV, HH, bufA, DwH, Db,
                                                        nullptr, nullptr, out, 0, 0, BB);

    // ---- Phase A tail on stream 0 (t=0 logits path) ----
    small_gemm<1>(EE, HH, 32, h01, Fw + Wstride, Fb + EE, nullptr, xt2, nullptr,
                  0, 0, part, 0);
    small_gemm<3>(VV, HH, 8, xt2, Dw, Db, nullptr, nullptr, out, 0, 0, part, 0);

    // ---- join ----
    cudaEventRecord(evJoin, s2);
    cudaStreamWaitEvent(0, evJoin, 0);
}

// round 14
// speedup vs baseline: 1.2835x; 1.0324x over previous
#include <cuda_runtime.h>
#include <cuda_fp16.h>
#include <cstddef>
#include <cstdint>

// Problem constants (fixed by the dataset)
#define TT 128
#define BB 64
#define EE 1024
#define HH 1024
#define VV 10000
#define LL 2

#define MREST (127 * 64)   // 8128 rows for t = 1..127
#define MHALF0 4096        // rows 0..4095   (t = 1..64)
#define MHALF1 (MREST - MHALF0)   // 4032 rows (t = 65..127)

// ---------------- scratch (device globals; no allocations allowed) ----------
__device__ __align__(256) __half g_bufA[MREST * 1024];
__device__ __align__(256) __half g_bufB[MREST * 1024];
__device__ __align__(256) float  g_raw [MREST * 1024];  // raw L0 accumulators
__device__ float g_x0 [BB * EE];
__device__ float g_xt [BB * EE];
__device__ float g_xt2[BB * EE];
__device__ float g_h0 [2 * BB * HH];           // h00 | h01
__device__ float g_aU [2 * BB * HH];           // aU0 | aU1
__device__ float g_part[8 * 64 * 10016];       // split-K partials
__device__ __align__(256) __half g_WwH[LL * HH * EE];   // fp16 weights
__device__ __align__(256) __half g_FwH[LL * EE * HH];
__device__ __align__(256) __half g_DwH[VV * HH];

// ---------------- fp32 -> fp16 weight conversion ----------------------------
__global__ void f2h_kernel(const float* __restrict__ src,
                           __half* __restrict__ dst, int n4)
{
    int i = blockIdx.x * blockDim.x + threadIdx.x;
    if (i >= n4) return;
    float4 v = reinterpret_cast<const float4*>(src)[i];
    __half2 lo = __floats2half2_rn(v.x, v.y);
    __half2 hi = __floats2half2_rn(v.z, v.w);
    uint2 o;
    o.x = *reinterpret_cast<unsigned*>(&lo);
    o.y = *reinterpret_cast<unsigned*>(&hi);
    reinterpret_cast<uint2*>(dst)[i] = o;
}

// ---------------- embedding gathers ------------------------------------------
__global__ void gather_emb_f(const int* __restrict__ inputs,
                             const float* __restrict__ emb,
                             float* __restrict__ X,
                             int ioff, int nrows)
{
    int idx = blockIdx.x * blockDim.x + threadIdx.x;
    int total = nrows * 256;
    if (idx >= total) return;
    int r = idx >> 8;
    int c = idx & 255;
    int tok = inputs[r + ioff];
    reinterpret_cast<float4*>(X)[(size_t)r * 256 + c] =
        reinterpret_cast<const float4*>(emb)[(size_t)tok * 256 + c];
}

__global__ void gather_emb_h(const int* __restrict__ inputs,
                             const float* __restrict__ emb,
                             __half* __restrict__ X,
                             int ioff, int nrows)
{
    int idx = blockIdx.x * blockDim.x + threadIdx.x;
    int total = nrows * 256;
    if (idx >= total) return;
    int r = idx >> 8;
    int c = idx & 255;
    int tok = inputs[r + ioff];
    float4 v = reinterpret_cast<const float4*>(emb)[(size_t)tok * 256 + c];
    __half2 lo = __floats2half2_rn(v.x, v.y);
    __half2 hi = __floats2half2_rn(v.z, v.w);
    uint2 o;
    o.x = *reinterpret_cast<unsigned*>(&lo);
    o.y = *reinterpret_cast<unsigned*>(&hi);
    reinterpret_cast<uint2*>(X)[(size_t)r * 256 + c] = o;
}

// ---------------- deferred aU epilogue for Phase-B layer 0 -------------------
// local rows [0, nrows); global row = mbase + m (mbase % 64 == 0)
__global__ void aU_epi(const float* __restrict__ raw,
                       const float* __restrict__ Wb,
                       const float* __restrict__ aU,
                       __half* __restrict__ Xout,
                       float* __restrict__ hall, int l, int t0, int nrows)
{
    int idx = blockIdx.x * blockDim.x + threadIdx.x;
    if (idx >= nrows * 256) return;
    int m = idx >> 8;
    int c = idx & 255;
    int n = c * 4;

    float4 v  = reinterpret_cast<const float4*>(raw)[(size_t)m * 256 + c];
    float4 b  = *reinterpret_cast<const float4*>(&Wb[n]);
    float4 au = *reinterpret_cast<const float4*>(&aU[(size_t)(m & 63) * HH + n]);
    float v0 = tanhf((v.x + b.x) + au.x);
    float v1 = tanhf((v.y + b.y) + au.y);
    float v2 = tanhf((v.z + b.z) + au.z);
    float v3 = tanhf((v.w + b.w) + au.w);

    __half2 lo = __floats2half2_rn(v0, v1);
    __half2 hi = __floats2half2_rn(v2, v3);
    uint2 o;
    o.x = *reinterpret_cast<unsigned*>(&lo);
    o.y = *reinterpret_cast<unsigned*>(&hi);
    reinterpret_cast<uint2*>(Xout)[(size_t)m * 256 + c] = o;

    int t = t0 + (m >> 6);
    int bb = m & 63;
    *reinterpret_cast<float4*>(&hall[(((size_t)t * LL + l) * BB + bb) * HH + n]) =
        make_float4(v0, v1, v2, v3);
}

// =======================================================================
// Small-M (M=64) split-K fp32 GEMM (Phase A), batchable via grid.z
// =======================================================================
__global__ __launch_bounds__(256)
void sgemm_splitk(int N, int K,
                  const float* __restrict__ A,
                  const float* __restrict__ W,
                  float* __restrict__ partial,
                  size_t aStride, size_t wStride, size_t pStride)
{
    const float* Ab = A + blockIdx.z * aStride;
    const float* Wb = W + blockIdx.z * wStride;
    float* Pb = partial + blockIdx.z * pStride;

    __shared__ float As[8][68];
    __shared__ float Ws[8][68];

    const int tid = threadIdx.x;
    const int bn  = blockIdx.x * 64;
    const int s   = blockIdx.y;
    const int kc  = K / gridDim.y;
    const int k0  = s * kc;

    const int tx = tid & 15;
    const int ty = tid >> 4;
    const int lr = tid >> 2;
    const int lk = (tid & 3) * 2;

    float acc[4][4];
#pragma unroll
    for (int i = 0; i < 4; i++)
#pragma unroll
        for (int j = 0; j < 4; j++) acc[i][j] = 0.0f;

    const int gn = bn + lr;
    const bool okW = gn < N;

    for (int kk = 0; kk < kc; kk += 8) {
        float2 av = *reinterpret_cast<const float2*>(&Ab[(size_t)lr * K + k0 + kk + lk]);
        float2 wv = make_float2(0.f, 0.f);
        if (okW)
            wv = *reinterpret_cast<const float2*>(&Wb[(size_t)gn * K + k0 + kk + lk]);
        As[lk][lr] = av.x;  As[lk + 1][lr] = av.y;
        Ws[lk][lr] = wv.x;  Ws[lk + 1][lr] = wv.y;
        __syncthreads();

#pragma unroll
        for (int k = 0; k < 8; k++) {
            float a[4], b[4];
#pragma unroll
            for (int i = 0; i < 4; i++) a[i] = As[k][ty * 4 + i];
#pragma unroll
            for (int j = 0; j < 4; j++) b[j] = Ws[k][tx * 4 + j];
#pragma unroll
            for (int i = 0; i < 4; i++)
#pragma unroll
                for (int j = 0; j < 4; j++)
                    acc[i][j] = fmaf(a[i], b[j], acc[i][j]);
        }
        __syncthreads();
    }

#pragma unroll
    for (int i = 0; i < 4; i++) {
        int m = ty * 4 + i;
#pragma unroll
        for (int j = 0; j < 4; j++) {
            int n = bn + tx * 4 + j;
            if (n < N)
                Pb[((size_t)s * 64 + m) * N + n] = acc[i][j];
        }
    }
}

template <int EPI>
__global__ void splitk_epi(int N, int nsplit,
                           const float* __restrict__ partial,
                           const float* __restrict__ bias,
                           const float* __restrict__ aU,
                           float* __restrict__ C,
                           float* __restrict__ O,
                           int l, int row_off,
                           size_t pStride, size_t bStride, size_t cStride)
{
    const float* Pb = partial + blockIdx.y * pStride;
    const float* Bb = bias + blockIdx.y * bStride;
    float* Cb = C ? C + blockIdx.y * cStride : nullptr;

    int idx = blockIdx.x * blockDim.x + threadIdx.x;
    if (idx >= 64 * N) return;
    int m = idx / N;
    int n = idx - m * N;
    float acc = 0.0f;
    for (int s = 0; s < nsplit; s++)
        acc += Pb[((size_t)s * 64 + m) * N + n];
    float v = acc + Bb[n];
    if (EPI == 0) {
        Cb[(size_t)m * N + n] = v;
    } else if (EPI == 1) {
        Cb[(size_t)m * N + n] = tanhf(v);
    } else if (EPI == 2) {
        v += aU[(size_t)m * N + n];
        v = tanhf(v);
        Cb[(size_t)m * N + n] = v;
        O[(((size_t)0 * LL + l) * BB + m) * HH + n] = v;
    } else { // EPI == 3
        O[(size_t)(m + row_off) * N + n] = v;
    }
}

// =======================================================================
// Big GEMM on tensor cores: fp16 mma.sync.m16n8k16 + ldmatrix,
// 3-stage cp.async pipeline, 128x256 block tile, 8 warps of 64x64.
// EPI 0: O_raw[gm*N+gn] = acc (fp32, no bias) — for deferred epilogue.
// =======================================================================
#define CBM 128
#define CBN 256
#define CBK 32
#define NSTG 3
#define HSTR 40
#define ABUF_BYTES (CBM * HSTR * 2)
#define WBUF_BYTES (CBN * HSTR * 2)
#define SMEM_BYTES (NSTG * (ABUF_BYTES + WBUF_BYTES))

__device__ __forceinline__ void cp_async16(uint32_t saddr, const void* gptr, bool ok) {
    int sz = ok ? 16 : 0;
    asm volatile("cp.async.cg.shared.global [%0], [%1], 16, %2;\n"
                 :: "r"(saddr), "l"(gptr), "r"(sz));
}

__device__ __forceinline__ void mma_f16(float c[4], const unsigned a[4],
                                        unsigned b0, unsigned b1) {
    asm volatile("mma.sync.aligned.m16n8k16.row.col.f32.f16.f16.f32 "
                 "{%0,%1,%2,%3}, {%4,%5,%6,%7}, {%8,%9}, {%0,%1,%2,%3};"
                 : "+f"(c[0]), "+f"(c[1]), "+f"(c[2]), "+f"(c[3])
                 : "r"(a[0]), "r"(a[1]), "r"(a[2]), "r"(a[3]),
                   "r"(b0), "r"(b1));
}

__device__ __forceinline__ void ldsm_x4(unsigned r[4], uint32_t saddr) {
    asm volatile("ldmatrix.sync.aligned.m8n8.x4.shared.b16 {%0,%1,%2,%3}, [%4];"
                 : "=r"(r[0]), "=r"(r[1]), "=r"(r[2]), "=r"(r[3]) : "r"(saddr));
}

template <int EPI>
__global__ __launch_bounds__(256, 1)
void hgemm(int M, int N, int K,
           const __half* __restrict__ A,
           const __half* __restrict__ W,
           const float* __restrict__ bias,
           const float* __restrict__ aU,
           __half* __restrict__ C,
           float* __restrict__ O,
           int t0, int l, int row_off)
{
    extern __shared__ char smraw[];

    const int tid  = threadIdx.x;
    const int lane = tid & 31;
    const int wid  = tid >> 5;
    const int wm   = (wid & 1) * 64;
    const int wn   = (wid >> 1) * 64;
    const int grp  = lane >> 2;
    const int tig  = lane & 3;

    const int bm = blockIdx.x * CBM;
    const int bn = blockIdx.y * CBN;

    uint32_t sbase;
    asm("{ .reg .u64 t; cvta.to.shared.u64 t, %1; cvt.u32.u64 %0, t; }"
        : "=r"(sbase) : "l"(smraw));

    bool aok[2];  const __half* agp[2];  uint32_t asm_[2];
#pragma unroll
    for (int i = 0; i < 2; i++) {
        int slot = tid + 256 * i;
        int row = slot >> 2, seg = slot & 3;
        aok[i] = (bm + row) < M;
        agp[i] = A + (size_t)(aok[i] ? bm + row : 0) * K + seg * 8;
        asm_[i] = sbase + (uint32_t)(row * (HSTR * 2) + seg * 16);
    }
    bool wok[4];  const __half* wgp[4];  uint32_t wsm_[4];
#pragma unroll
    for (int i = 0; i < 4; i++) {
        int slot = tid + 256 * i;
        int row = slot >> 2, seg = slot & 3;
        wok[i] = (bn + row) < N;
        wgp[i] = W + (size_t)(wok[i] ? bn + row : 0) * K + seg * 8;
        wsm_[i] = sbase + (uint32_t)(NSTG * ABUF_BYTES + row * (HSTR * 2) + seg * 16);
    }

    const int lrow = lane & 15;
    const int lcol = lane >> 4;
    uint32_t aoff[4], boff[4];
#pragma unroll
    for (int mf = 0; mf < 4; mf++)
        aoff[mf] = (uint32_t)((wm + mf * 16 + lrow) * (HSTR * 2) + lcol * 16);
#pragma unroll
    for (int p = 0; p < 4; p++)
        boff[p] = (uint32_t)((wn + p * 16 + lrow) * (HSTR * 2) + lcol * 16);

    float acc[4][8][4];
#pragma unroll
    for (int mf = 0; mf < 4; mf++)
#pragma unroll
        for (int nf = 0; nf < 8; nf++)
#pragma unroll
            for (int r = 0; r < 4; r++) acc[mf][nf][r] = 0.0f;

    const int kT = K / CBK;

#pragma unroll
    for (int s = 0; s < NSTG - 1; s++) {
#pragma unroll
        for (int i = 0; i < 2; i++)
            cp_async16(asm_[i] + s * ABUF_BYTES, agp[i] + s * CBK, aok[i]);
#pragma unroll
        for (int i = 0; i < 4; i++)
            cp_async16(wsm_[i] + s * WBUF_BYTES, wgp[i] + s * CBK, wok[i]);
        asm volatile("cp.async.commit_group;\n");
    }

    for (int kt = 0; kt < kT; kt++) {
        asm volatile("cp.async.wait_group %0;\n" :: "n"(NSTG - 2));
        __syncthreads();

        const int pf = kt + NSTG - 1;
        if (pf < kT) {
            const int ps = pf % NSTG;
#pragma unroll
            for (int i = 0; i < 2; i++)
                cp_async16(asm_[i] + ps * ABUF_BYTES, agp[i] + pf * CBK, aok[i]);
#pragma unroll
            for (int i = 0; i < 4; i++)
                cp_async16(wsm_[i] + ps * WBUF_BYTES, wgp[i] + pf * CBK, wok[i]);
        }
        asm volatile("cp.async.commit_group;\n");

        const int cb = kt % NSTG;
        const uint32_t abase = sbase + cb * ABUF_BYTES;
        const uint32_t wbase = sbase + NSTG * ABUF_BYTES + cb * WBUF_BYTES;

#pragma unroll
        for (int ks = 0; ks < 2; ks++) {
            const uint32_t kb = ks * 32;
            unsigned af[4][4], bf[4][4];
#pragma unroll
            for (int mf = 0; mf < 4; mf++)
                ldsm_x4(af[mf], abase + aoff[mf] + kb);
#pragma unroll
            for (int p = 0; p < 4; p++)
                ldsm_x4(bf[p], wbase + boff[p] + kb);
#pragma unroll
            for (int mf = 0; mf < 4; mf++)
#pragma unroll
                for (int p = 0; p < 4; p++) {
                    mma_f16(acc[mf][2 * p],     af[mf], bf[p][0], bf[p][2]);
                    mma_f16(acc[mf][2 * p + 1], af[mf], bf[p][1], bf[p][3]);
                }
        }
    }

    // ---- epilogue ----
#pragma unroll
    for (int mf = 0; mf < 4; mf++) {
#pragma unroll
        for (int rh = 0; rh < 2; rh++) {
            int gm = bm + wm + mf * 16 + grp + rh * 8;
            if (gm >= M) continue;
#pragma unroll
            for (int nf = 0; nf < 8; nf++) {
                int gn = bn + wn + nf * 8 + tig * 2;
                if (gn >= N) continue;
                if (EPI == 0) {
                    *reinterpret_cast<float2*>(&O[(size_t)gm * N + gn]) =
                        make_float2(acc[mf][nf][rh * 2 + 0], acc[mf][nf][rh * 2 + 1]);
                    continue;
                }
                float v0 = acc[mf][nf][rh * 2 + 0] + bias[gn];
                float v1 = acc[mf][nf][rh * 2 + 1] + bias[gn + 1];
                if (EPI == 1) {
                    v0 = tanhf(v0); v1 = tanhf(v1);
                    __half2 h = __floats2half2_rn(v0, v1);
                    *reinterpret_cast<__half2*>(&C[(size_t)gm * N + gn]) = h;
                } else if (EPI == 2) {
                    const float2 au = *reinterpret_cast<const float2*>(
                        &aU[(size_t)(gm & 63) * N + gn]);
                    v0 = tanhf(v0 + au.x);
                    v1 = tanhf(v1 + au.y);
                    __half2 h = __floats2half2_rn(v0, v1);
                    *reinterpret_cast<__half2*>(&C[(size_t)gm * N + gn]) = h;
                    int t = t0 + (gm >> 6);
                    int b = gm & 63;
                    *reinterpret_cast<float2*>(
                        &O[(((size_t)t * LL + l) * BB + b) * HH + gn]) =
                        make_float2(v0, v1);
                } else { // EPI == 3
                    *reinterpret_cast<float2*>(&O[(size_t)(gm + row_off) * N + gn]) =
                        make_float2(v0, v1);
                }
            }
        }
    }
}

// ---------------- host-side orchestration -----------------------------------
static inline dim3 hgrid(int M, int N) {
    return dim3((M + CBM - 1) / CBM, (N + CBN - 1) / CBN);
}

template <int EPI>
static void small_gemm(int N, int K, int nsplit,
                       const float* A, const float* W, const float* bias,
                       const float* aU, float* C, float* O,
                       int l, int row_off, float* part, cudaStream_t st)
{
    dim3 g((N + 63) / 64, nsplit, 1);
    sgemm_splitk<<<g, 256, 0, st>>>(N, K, A, W, part, 0, 0, 0);
    int total = 64 * N;
    splitk_epi<EPI><<<dim3((total + 255) / 256, 1), 256, 0, st>>>(
        N, nsplit, part, bias, aU, C, O, l, row_off, 0, 0, 0);
}

static void small_gemm_pair(int N, int K, int nsplit,
                            const float* A, size_t aStr,
                            const float* W, size_t wStr,
                            const float* bias, size_t bStr,
                            float* C, size_t cStr, float* part, cudaStream_t st)
{
    size_t pStr = (size_t)nsplit * 64 * N;
    dim3 g((N + 63) / 64, nsplit, 2);
    sgemm_splitk<<<g, 256, 0, st>>>(N, K, A, W, part, aStr, wStr, pStr);
    int total = 64 * N;
    splitk_epi<0><<<dim3((total + 255) / 256, 2), 256, 0, st>>>(
        N, nsplit, part, bias, nullptr, C, nullptr, 0, 0, pStr, bStr, cStr);
}

extern "C" void kernel_launch(void* const* d_in, const int* in_sizes, int n_in,
                              void* d_out, int out_size)
{
    (void)in_sizes; (void)n_in; (void)out_size;
    const int*   inputs = (const int*)  d_in[0];
    const float* hidden = (const float*)d_in[1];   // (L,B,H)
    const float* emb    = (const float*)d_in[2];   // (V,E)
    const float* Ww     = (const float*)d_in[3];   // (L,H,E)
    const float* Wb     = (const float*)d_in[4];   // (L,H)
    const float* Uw     = (const float*)d_in[5];   // (L,H,H)
    const float* Ub     = (const float*)d_in[6];   // (L,H)
    const float* Fw     = (const float*)d_in[7];   // (L,E,H)
    const float* Fb     = (const float*)d_in[8];   // (L,E)
    const float* Dw     = (const float*)d_in[9];   // (V,H)
    const float* Db     = (const float*)d_in[10];  // (V,)

    float* out  = (float*)d_out;
    float* hall = out + (size_t)TT * BB * VV;      // h_all after logits

    __half *bufA, *bufB, *WwH, *FwH, *DwH;
    float *x0, *xt, *xt2, *h0, *aU, *part, *raw;
    cudaGetSymbolAddress((void**)&bufA, g_bufA);
    cudaGetSymbolAddress((void**)&bufB, g_bufB);
    cudaGetSymbolAddress((void**)&raw,  g_raw);
    cudaGetSymbolAddress((void**)&x0,  g_x0);
    cudaGetSymbolAddress((void**)&xt,  g_xt);
    cudaGetSymbolAddress((void**)&xt2, g_xt2);
    cudaGetSymbolAddress((void**)&h0,  g_h0);
    cudaGetSymbolAddress((void**)&aU,  g_aU);
    cudaGetSymbolAddress((void**)&part, g_part);
    cudaGetSymbolAddress((void**)&WwH, g_WwH);
    cudaGetSymbolAddress((void**)&FwH, g_FwH);
    cudaGetSymbolAddress((void**)&DwH, g_DwH);

    float* h00 = h0;
    float* h01 = h0 + (size_t)BB * HH;
    float* aU0 = aU;
    float* aU1 = aU + (size_t)BB * HH;

    cudaFuncSetAttribute(hgemm<0>, cudaFuncAttributeMaxDynamicSharedMemorySize, SMEM_BYTES);
    cudaFuncSetAttribute(hgemm<1>, cudaFuncAttributeMaxDynamicSharedMemorySize, SMEM_BYTES);
    cudaFuncSetAttribute(hgemm<2>, cudaFuncAttributeMaxDynamicSharedMemorySize, SMEM_BYTES);
    cudaFuncSetAttribute(hgemm<3>, cudaFuncAttributeMaxDynamicSharedMemorySize, SMEM_BYTES);

    const size_t Wstride = (size_t)HH * EE;
    const size_t BH = (size_t)BB * HH;

    static cudaStream_t s2 = nullptr, s3 = nullptr;
    static cudaEvent_t evFork = nullptr, evPrep = nullptr, evAU0 = nullptr,
                       evAU1 = nullptr, evJoin2 = nullptr, evJoin3 = nullptr;
    if (s2 == nullptr) {
        cudaStreamCreateWithFlags(&s2, cudaStreamNonBlocking);
        cudaStreamCreateWithFlags(&s3, cudaStreamNonBlocking);
        cudaEventCreateWithFlags(&evFork,  cudaEventDisableTiming);
        cudaEventCreateWithFlags(&evPrep,  cudaEventDisableTiming);
        cudaEventCreateWithFlags(&evAU0,   cudaEventDisableTiming);
        cudaEventCreateWithFlags(&evAU1,   cudaEventDisableTiming);
        cudaEventCreateWithFlags(&evJoin2, cudaEventDisableTiming);
        cudaEventCreateWithFlags(&evJoin3, cudaEventDisableTiming);
    }

    // half-split pointers (split at row 4096 = t boundary 65)
    __half* bufA1 = bufA + (size_t)MHALF0 * HH;
    __half* bufB1 = bufB + (size_t)MHALF0 * HH;
    float*  raw1  = raw  + (size_t)MHALF0 * HH;
    const int T0_H0 = 1;                 // t0 for half 0
    const int T0_H1 = 1 + MHALF0 / 64;   // t0 for half 1 (= 65)

    // ---- fork: stream2 does conversion + gather, then signals s3 ----
    cudaEventRecord(evFork, 0);
    cudaStreamWaitEvent(s2, evFork, 0);
    {
        int n4;
        n4 = (LL * HH * EE) / 4;
        f2h_kernel<<<(n4 + 255) / 256, 256, 0, s2>>>(Ww, WwH, n4);
        n4 = (LL * EE * HH) / 4;
        f2h_kernel<<<(n4 + 255) / 256, 256, 0, s2>>>(Fw, FwH, n4);
        n4 = (VV * HH) / 4;
        f2h_kernel<<<(n4 + 255) / 256, 256, 0, s2>>>(Dw, DwH, n4);
        gather_emb_h<<<(MREST * 256 + 255) / 256, 256, 0, s2>>>(inputs, emb, bufA,
                                                                BB, MREST);
    }
    cudaEventRecord(evPrep, s2);
    cudaStreamWaitEvent(s3, evPrep, 0);

    // ---- L0 mainloops (no aU dependency) on both halves ----
    hgemm<0><<<hgrid(MHALF0, HH), 256, SMEM_BYTES, s2>>>(MHALF0, HH, EE, bufA, WwH,
                                                         nullptr, nullptr, nullptr,
                                                         raw, 0, 0, 0);
    hgemm<0><<<hgrid(MHALF1, HH), 256, SMEM_BYTES, s3>>>(MHALF1, HH, EE, bufA1, WwH,
                                                         nullptr, nullptr, nullptr,
                                                         raw1, 0, 0, 0);

    // ---- Phase A on stream 0 (hidden under L0 mainloops) ----
    gather_emb_f<<<(BB * 256 + 255) / 256, 256>>>(inputs, emb, x0, 0, BB);
    small_gemm_pair(HH, HH, 32, hidden, BH, Uw, Wstride, Ub, HH, aU, BH, part, 0);
    small_gemm<2>(HH, EE, 32, x0, Ww, Wb, aU0, h00, hall, 0, 0, part, 0);
    small_gemm<0>(HH, HH, 32, h00, Uw, Ub, nullptr, aU0, nullptr, 0, 0, part, 0);
    cudaEventRecord(evAU0, 0);
    cudaStreamWaitEvent(s2, evAU0, 0);
    cudaStreamWaitEvent(s3, evAU0, 0);

    // ---- deferred L0 epilogue + F0, per half ----
    aU_epi<<<(MHALF0 * 256 + 255) / 256, 256, 0, s2>>>(raw, Wb, aU0, bufB, hall,
                                                       0, T0_H0, MHALF0);
    hgemm<1><<<hgrid(MHALF0, EE), 256, SMEM_BYTES, s2>>>(MHALF0, EE, HH, bufB, FwH, Fb,
                                                         nullptr, bufA, nullptr, 0, 0, 0);
    aU_epi<<<(MHALF1 * 256 + 255) / 256, 256, 0, s3>>>(raw1, Wb, aU0, bufB1, hall,
                                                       0, T0_H1, MHALF1);
    hgemm<1><<<hgrid(MHALF1, EE), 256, SMEM_BYTES, s3>>>(MHALF1, EE, HH, bufB1, FwH, Fb,
                                                         nullptr, bufA1, nullptr, 0, 0, 0);

    // ---- Phase A continues on stream 0 ----
    small_gemm<1>(EE, HH, 32, h00, Fw, Fb, nullptr, xt, nullptr, 0, 0, part, 0);
    small_gemm<2>(HH, EE, 32, xt, Ww + Wstride, Wb + HH, aU1, h01, hall, 1, 0, part, 0);
    small_gemm<0>(HH, HH, 32, h01, Uw + Wstride, Ub + HH, nullptr, aU1, nullptr,
                  0, 0, part, 0);
    cudaEventRecord(evAU1, 0);
    cudaStreamWaitEvent(s2, evAU1, 0);
    cudaStreamWaitEvent(s3, evAU1, 0);

    // ---- layer 1 + F1 + logits, per half ----
    hgemm<2><<<hgrid(MHALF0, HH), 256, SMEM_BYTES, s2>>>(MHALF0, HH, EE, bufA,
                                                         WwH + Wstride, Wb + HH,
                                                         aU1, bufB, hall, T0_H0, 1, 0);
    hgemm<1><<<hgrid(MHALF0, EE), 256, SMEM_BYTES, s2>>>(MHALF0, EE, HH, bufB,
                                                         FwH + Wstride, Fb + EE,
                                                         nullptr, bufA, nullptr, 0, 0, 0);
    hgemm<3><<<hgrid(MHALF0, VV), 256, SMEM_BYTES, s2>>>(MHALF0, VV, HH, bufA, DwH, Db,
                                                         nullptr, nullptr, out,
                                                         0, 0, BB);
    hgemm<2><<<hgrid(MHALF1, HH), 256, SMEM_BYTES, s3>>>(MHALF1, HH, EE, bufA1,
                                                         WwH + Wstride, Wb + HH,
                                                         aU1, bufB1, hall, T0_H1, 1, 0);
    hgemm<1><<<hgrid(MHALF1, EE), 256, SMEM_BYTES, s3>>>(MHALF1, EE, HH, bufB1,
                                                         FwH + Wstride, Fb + EE,
                                                         nullptr, bufA1, nullptr, 0, 0, 0);
    hgemm<3><<<hgrid(MHALF1, VV), 256, SMEM_BYTES, s3>>>(MHALF1, VV, HH, bufA1, DwH, Db,
                                                         nullptr, nullptr, out,
                                                         0, 0, BB + MHALF0);

    // ---- Phase A tail on stream 0 (t=0 logits path) ----
    small_gemm<1>(EE, HH, 32, h01, Fw + Wstride, Fb + EE, nullptr, xt2, nullptr,
                  0, 0, part, 0);
    small_gemm<3>(VV, HH, 8, xt2, Dw, Db, nullptr, nullptr, out, 0, 0, part, 0);

    // ---- join ----
    cudaEventRecord(evJoin2, s2);
    cudaEventRecord(evJoin3, s3);
    cudaStreamWaitEvent(0, evJoin2, 0);
    cudaStreamWaitEvent(0, evJoin3, 0);
}